// round 5
// baseline (speedup 1.0000x reference)
#include <cuda_runtime.h>
#include <cuda_bf16.h>
#include <math.h>
#include <stdint.h>

// ---------------------------------------------------------------------------
// Problem constants
// ---------------------------------------------------------------------------
#define NBATCH   4
#define HDIM     128
#define WDIM     128
#define DM       768
#define NHEADS   12
#define DHEAD    64
#define DFF      2048
#define DC       768
#define WS       8
#define SHIFT    4
#define TOKENS   (NBATCH * HDIM * WDIM)          // 65536
#define NWIN     (NBATCH * NHEADS * 16 * 16)     // 12288
#define EPSV     1e-6f

// ---------------------------------------------------------------------------
// Scratch
// ---------------------------------------------------------------------------
#define W_QKV_SZ (3 * DM * DM)
#define W_OUT_SZ (DM * DM)
#define W_UP_SZ  (2 * DFF * DM)
#define W_DN_SZ  (DM * DFF)
#define W_TOTAL  (W_QKV_SZ + W_OUT_SZ + W_UP_SZ + W_DN_SZ)

__device__ float g_scale1[NBATCH * DM];
__device__ float g_scale2[NBATCH * DM];
__device__ float g_qkv [(size_t)TOKENS * 2 * DM];     // q,k only (ldc=1536)
__device__ float g_qw  [(size_t)NWIN * 64 * 64];
__device__ float g_kw  [(size_t)NWIN * 64 * 64];
__device__ float g_vw  [(size_t)NWIN * 64 * 64];
__device__ float g_ow  [(size_t)NWIN * 64 * 64];
__device__ float g_x2  [(size_t)TOKENS * DM];

__device__ __nv_bfloat16 g_h_hi [(size_t)TOKENS * DM];
__device__ __nv_bfloat16 g_h_lo [(size_t)TOKENS * DM];
__device__ __nv_bfloat16 g_oi_hi[(size_t)TOKENS * DM];
__device__ __nv_bfloat16 g_oi_lo[(size_t)TOKENS * DM];
__device__ __nv_bfloat16 g_a_hi [(size_t)TOKENS * DFF];
__device__ __nv_bfloat16 g_a_lo [(size_t)TOKENS * DFF];
__device__ __nv_bfloat16 g_w_hi [W_TOTAL];
__device__ __nv_bfloat16 g_w_lo [W_TOTAL];

__device__ __forceinline__ void split2(float v, __nv_bfloat16* hi, __nv_bfloat16* lo) {
    __nv_bfloat16 h = __float2bfloat16(v);
    *hi = h;
    *lo = __float2bfloat16(v - __bfloat162float(h));
}

// ---------------------------------------------------------------------------
// PTX helpers (sm_80+ features only; legal under compute_103)
// ---------------------------------------------------------------------------
__device__ __forceinline__ uint32_t smem_to_u32(const void* p) {
    uint32_t a;
    asm("{ .reg .u64 t; cvta.to.shared.u64 t, %1; cvt.u32.u64 %0, t; }" : "=r"(a) : "l"(p));
    return a;
}
#define CP_ASYNC16(sa, gp) \
    asm volatile("cp.async.cg.shared.global [%0], [%1], 16;" :: "r"(sa), "l"(gp))
#define CP_COMMIT() asm volatile("cp.async.commit_group;" ::: "memory")
#define CP_WAIT1()  asm volatile("cp.async.wait_group 1;" ::: "memory")
#define CP_WAIT0()  asm volatile("cp.async.wait_group 0;" ::: "memory")

__device__ __forceinline__ void ldsm_x4(uint32_t& r0, uint32_t& r1, uint32_t& r2,
                                        uint32_t& r3, uint32_t addr) {
    asm volatile("ldmatrix.sync.aligned.m8n8.x4.shared.b16 {%0,%1,%2,%3}, [%4];"
                 : "=r"(r0), "=r"(r1), "=r"(r2), "=r"(r3) : "r"(addr));
}
__device__ __forceinline__ void mma_bf16(float c[4], const uint32_t a[4],
                                         const uint32_t b[2]) {
    asm volatile("mma.sync.aligned.m16n8k16.row.col.f32.bf16.bf16.f32 "
                 "{%0,%1,%2,%3},{%4,%5,%6,%7},{%8,%9},{%0,%1,%2,%3};"
                 : "+f"(c[0]), "+f"(c[1]), "+f"(c[2]), "+f"(c[3])
                 : "r"(a[0]), "r"(a[1]), "r"(a[2]), "r"(a[3]),
                   "r"(b[0]), "r"(b[1]));
}

// window-scatter address helper (roll +4,+4 then 8x8 windows)
__device__ __forceinline__ size_t win_addr(int t, int h, int e) {
    int n = t >> 14;
    int y = (t >> 7) & 127;
    int x = t & 127;
    int Y = (y + SHIFT) & 127, X = (x + SHIFT) & 127;
    int wyx  = ((Y >> 3) << 4) + (X >> 3);
    int spos = ((Y & 7) << 3) + (X & 7);
    return ((size_t)((n * NHEADS + h) * 256 + wyx)) * 4096 + (size_t)spos * 64 + e;
}

// ---------------------------------------------------------------------------
// GEMM: 128x128x32 CTA tile, 4 warps (2m x 2n), warp tile 64x64, bf16x3.
// mode 0: C[row*ldc+col] = (D?D:0) + A@B^T
// mode 1: fused gated-GELU epilogue -> g_a_hi/g_a_lo (weights pre-interleaved)
// mode 2: qkv epilogue: cols<1536 -> C (ldc), cols>=1536 -> scatter V to g_vw
// ---------------------------------------------------------------------------
#define BKC     32
#define PADK    40
#define TILE_E  (128 * PADK)
#define STAGE_E (4 * TILE_E)
#define GEMM_SMEM (2 * STAGE_E * 2)     // 81920 bytes

__global__ __launch_bounds__(128) void hgemm_kernel(
    const __nv_bfloat16* __restrict__ Ahi, const __nv_bfloat16* __restrict__ Alo,
    const __nv_bfloat16* __restrict__ Bhi, const __nv_bfloat16* __restrict__ Blo,
    const float* __restrict__ Dres, float* __restrict__ C,
    int M, int N, int K, int ldc, int mode)
{
    extern __shared__ __align__(128) char smem[];
    const uint32_t sbase = smem_to_u32(smem);
    const int tid = threadIdx.x, lane = tid & 31, wid = tid >> 5;
    const int wm = wid >> 1, wn = wid & 1;
    const size_t bm = (size_t)blockIdx.y * 128;
    const size_t bn = (size_t)blockIdx.x * 128;

    const __nv_bfloat16* gsrc[4] = { Ahi + bm * (size_t)K, Alo + bm * (size_t)K,
                                     Bhi + bn * (size_t)K, Blo + bn * (size_t)K };

    float acc[4][8][4];
    #pragma unroll
    for (int i = 0; i < 4; i++)
        #pragma unroll
        for (int j = 0; j < 8; j++)
            #pragma unroll
            for (int l = 0; l < 4; l++) acc[i][j][l] = 0.f;

    const int nstage = K / BKC;

    // 512 16B-transfers per matrix per stage; 128 threads -> 4 iters/matrix
    auto issue = [&](int st) {
        const int k0 = st * BKC;
        const uint32_t sb = sbase + (uint32_t)((st & 1) * STAGE_E * 2);
        #pragma unroll
        for (int m_ = 0; m_ < 4; m_++) {
            #pragma unroll
            for (int i = 0; i < 4; i++) {
                int idx = tid + i * 128;            // 0..511
                int row = idx >> 2, seg = (idx & 3) << 3;
                const __nv_bfloat16* gp = gsrc[m_] + (size_t)row * K + k0 + seg;
                uint32_t sa = sb + (uint32_t)((m_ * TILE_E + row * PADK + seg) * 2);
                CP_ASYNC16(sa, gp);
            }
        }
        CP_COMMIT();
    };

    issue(0);
    if (nstage > 1) issue(1);

    const int a_r = lane & 15, a_h = (lane >> 4) << 3;
    const int b_r = (lane & 7) + ((lane & 16) >> 1);
    const int b_k = lane & 8;

    for (int st = 0; st < nstage; st++) {
        if (st + 1 < nstage) { CP_WAIT1(); } else { CP_WAIT0(); }
        __syncthreads();

        const uint32_t sb = sbase + (uint32_t)((st & 1) * STAGE_E * 2);
        const uint32_t sAhi = sb;
        const uint32_t sAlo = sb + TILE_E * 2;
        const uint32_t sBhi = sb + 2 * TILE_E * 2;
        const uint32_t sBlo = sb + 3 * TILE_E * 2;

        #pragma unroll
        for (int kk = 0; kk < BKC; kk += 16) {
            uint32_t a[4][4], al[4][4], bh[8][2], bl[8][2];
            // A hi (4 m-tiles of 16 rows)
            #pragma unroll
            for (int mt = 0; mt < 4; mt++)
                ldsm_x4(a[mt][0], a[mt][1], a[mt][2], a[mt][3],
                        sAhi + (uint32_t)(((wm * 64 + mt * 16 + a_r) * PADK + kk + a_h) * 2));
            // B hi (8 n-tiles of 8 via 4 x4-loads)
            #pragma unroll
            for (int p = 0; p < 4; p++) {
                uint32_t r0, r1, r2, r3;
                ldsm_x4(r0, r1, r2, r3,
                        sBhi + (uint32_t)(((wn * 64 + p * 16 + b_r) * PADK + kk + b_k) * 2));
                bh[p * 2][0] = r0; bh[p * 2][1] = r1;
                bh[p * 2 + 1][0] = r2; bh[p * 2 + 1][1] = r3;
            }
            #pragma unroll
            for (int mt = 0; mt < 4; mt++)
                #pragma unroll
                for (int nt = 0; nt < 8; nt++)
                    mma_bf16(acc[mt][nt], a[mt], bh[nt]);
            // B lo
            #pragma unroll
            for (int p = 0; p < 4; p++) {
                uint32_t r0, r1, r2, r3;
                ldsm_x4(r0, r1, r2, r3,
                        sBlo + (uint32_t)(((wn * 64 + p * 16 + b_r) * PADK + kk + b_k) * 2));
                bl[p * 2][0] = r0; bl[p * 2][1] = r1;
                bl[p * 2 + 1][0] = r2; bl[p * 2 + 1][1] = r3;
            }
            #pragma unroll
            for (int mt = 0; mt < 4; mt++)
                #pragma unroll
                for (int nt = 0; nt < 8; nt++)
                    mma_bf16(acc[mt][nt], a[mt], bl[nt]);
            // A lo
            #pragma unroll
            for (int mt = 0; mt < 4; mt++)
                ldsm_x4(al[mt][0], al[mt][1], al[mt][2], al[mt][3],
                        sAlo + (uint32_t)(((wm * 64 + mt * 16 + a_r) * PADK + kk + a_h) * 2));
            #pragma unroll
            for (int mt = 0; mt < 4; mt++)
                #pragma unroll
                for (int nt = 0; nt < 8; nt++)
                    mma_bf16(acc[mt][nt], al[mt], bh[nt]);
        }
        __syncthreads();
        if (st + 2 < nstage) issue(st + 2);
    }

    // ---------------- epilogue ----------------
    const int er = lane >> 2, ec = (lane & 3) * 2;

    if (mode == 1) {
        // fused gated GELU: col pair (even,odd) = (a_j, g_j); j = col/2
        #pragma unroll
        for (int mt = 0; mt < 4; mt++) {
            size_t r0 = bm + wm * 64 + mt * 16 + er;
            size_t r1 = r0 + 8;
            #pragma unroll
            for (int nt = 0; nt < 8; nt++) {
                int col = (int)bn + wn * 64 + nt * 8 + ec;
                int j = col >> 1;
                float a0 = acc[mt][nt][0], gg0 = acc[mt][nt][1];
                float a1 = acc[mt][nt][2], gg1 = acc[mt][nt][3];
                float v0 = a0 * (gg0 * 0.5f * (1.0f + erff(gg0 * 0.70710678118654752f)));
                float v1 = a1 * (gg1 * 0.5f * (1.0f + erff(gg1 * 0.70710678118654752f)));
                split2(v0, &g_a_hi[r0 * DFF + j], &g_a_lo[r0 * DFF + j]);
                split2(v1, &g_a_hi[r1 * DFF + j], &g_a_lo[r1 * DFF + j]);
            }
        }
        return;
    }

    if (mode == 2 && bn >= 1536) {
        // V region: scatter straight into windowed layout
        #pragma unroll
        for (int mt = 0; mt < 4; mt++) {
            int t0 = (int)bm + wm * 64 + mt * 16 + er;
            int t1 = t0 + 8;
            #pragma unroll
            for (int nt = 0; nt < 8; nt++) {
                int col = (int)bn + wn * 64 + nt * 8 + ec;
                int h = (col - 1536) >> 6;
                int e = col & 63;
                float2 v0 = make_float2(acc[mt][nt][0], acc[mt][nt][1]);
                float2 v1 = make_float2(acc[mt][nt][2], acc[mt][nt][3]);
                *(float2*)&g_vw[win_addr(t0, h, e)] = v0;
                *(float2*)&g_vw[win_addr(t1, h, e)] = v1;
            }
        }
        return;
    }

    // plain / q,k region
    #pragma unroll
    for (int mt = 0; mt < 4; mt++) {
        size_t row0 = bm + wm * 64 + mt * 16 + er;
        #pragma unroll
        for (int nt = 0; nt < 8; nt++) {
            size_t col = bn + wn * 64 + nt * 8 + ec;
            if (mode == 2 && col >= 1536) continue;
            float* p0 = C + row0 * (size_t)ldc + col;
            float* p1 = C + (row0 + 8) * (size_t)ldc + col;
            float2 v0 = make_float2(acc[mt][nt][0], acc[mt][nt][1]);
            float2 v1 = make_float2(acc[mt][nt][2], acc[mt][nt][3]);
            if (Dres) {
                const float2 d0 = *(const float2*)(Dres + row0 * (size_t)ldc + col);
                const float2 d1 = *(const float2*)(Dres + (row0 + 8) * (size_t)ldc + col);
                v0.x += d0.x; v0.y += d0.y; v1.x += d1.x; v1.y += d1.y;
            }
            *(float2*)p0 = v0;
            *(float2*)p1 = v1;
        }
    }
}

// ---------------------------------------------------------------------------
// K0: ada scales
// ---------------------------------------------------------------------------
__global__ void ada_kernel(const float* __restrict__ cond,
                           const float* __restrict__ w1,
                           const float* __restrict__ w2)
{
    int gw   = (blockIdx.x * blockDim.x + threadIdx.x) >> 5;
    int lane = threadIdx.x & 31;
    if (gw >= 2 * NBATCH * DM) return;
    int which = gw / (NBATCH * DM);
    int rem   = gw % (NBATCH * DM);
    int n = rem / DM, d = rem % DM;
    const float* w  = which ? w2 : w1;
    const float* cr = cond + n * DC;
    const float* wr = w + (size_t)d * DC;
    float s = 0.f;
    for (int i = lane; i < DC; i += 32) s += cr[i] * wr[i];
    #pragma unroll
    for (int o = 16; o; o >>= 1) s += __shfl_xor_sync(0xffffffffu, s, o);
    if (lane == 0) (which ? g_scale2 : g_scale1)[rem] = s + 1.0f;
}

// ---------------------------------------------------------------------------
// K1: RMSNorm * ada -> bf16 hi/lo
// ---------------------------------------------------------------------------
__global__ __launch_bounds__(256) void rmsnorm_kernel(const float* __restrict__ x,
                                                      const float* __restrict__ scale)
{
    int t = blockIdx.x;
    int n = t >> 14;
    const float* xr = x + (size_t)t * DM;
    float v[3]; float ss = 0.f;
    #pragma unroll
    for (int i = 0; i < 3; i++) { v[i] = xr[threadIdx.x + 256 * i]; ss += v[i] * v[i]; }
    __shared__ float red[8];
    #pragma unroll
    for (int o = 16; o; o >>= 1) ss += __shfl_xor_sync(0xffffffffu, ss, o);
    if ((threadIdx.x & 31) == 0) red[threadIdx.x >> 5] = ss;
    __syncthreads();
    if (threadIdx.x == 0) {
        float r = 0.f;
        #pragma unroll
        for (int i = 0; i < 8; i++) r += red[i];
        red[0] = r;
    }
    __syncthreads();
    float inv = rsqrtf(red[0] * (1.0f / DM) + EPSV);
    const float* sc = scale + (size_t)n * DM;
    #pragma unroll
    for (int i = 0; i < 3; i++) {
        int c = threadIdx.x + 256 * i;
        float o = v[i] * sc[c] * inv;
        split2(o, &g_h_hi[(size_t)t * DM + c], &g_h_lo[(size_t)t * DM + c]);
    }
}

// ---------------------------------------------------------------------------
// K2: weight split (optional row interleave for ff_up gating)
// ---------------------------------------------------------------------------
__global__ __launch_bounds__(256) void wsplit_kernel(const float* __restrict__ w,
                                                     __nv_bfloat16* __restrict__ hi,
                                                     __nv_bfloat16* __restrict__ lo,
                                                     int n, int rowlen, int perm)
{
    int i = blockIdx.x * 256 + threadIdx.x;
    if (i >= n) return;
    int dst = i;
    if (perm) {
        int r = i / rowlen, c = i % rowlen;
        int dr = (r < DFF) ? (2 * r) : (2 * (r - DFF) + 1);
        dst = dr * rowlen + c;
    }
    split2(w[i], &hi[dst], &lo[dst]);
}

// ---------------------------------------------------------------------------
// K3: q/k norm + RoPE + window scatter (v handled in GEMM epilogue)
// ---------------------------------------------------------------------------
__global__ __launch_bounds__(384) void qk_transform_kernel(const float* __restrict__ pos,
                                                           const float* __restrict__ attn_scale,
                                                           const float* __restrict__ rope_freqs)
{
    int t = blockIdx.x;
    int h = threadIdx.x >> 5;
    int l = threadIdx.x & 31;

    const float* base = g_qkv + (size_t)t * (2 * DM) + h * DHEAD;
    float q0 = base[l],          q1 = base[l + 32];
    float k0 = base[DM + l],     k1 = base[DM + l + 32];

    float sq = q0 * q0 + q1 * q1;
    float sk = k0 * k0 + k1 * k1;
    #pragma unroll
    for (int o = 16; o; o >>= 1) {
        sq += __shfl_xor_sync(0xffffffffu, sq, o);
        sk += __shfl_xor_sync(0xffffffffu, sk, o);
    }
    float ssh = sqrtf(attn_scale[h]);
    float rq = ssh * rsqrtf(sq + EPSV);
    float rk = ssh * rsqrtf(sk + EPSV);
    q0 *= rq; q1 *= rq; k0 *= rk; k1 *= rk;

    float p0 = pos[(size_t)t * 2 + 0];
    float p1 = pos[(size_t)t * 2 + 1];
    int f = l & 15;
    float freq = rope_freqs[h * 8 + (f & 7)];
    float th = (f < 8 ? p0 : p1) * freq;
    float c = cosf(th), s = sinf(th);
    float qp = __shfl_xor_sync(0xffffffffu, q0, 16);
    float kp = __shfl_xor_sync(0xffffffffu, k0, 16);
    if (l < 16) { q0 = q0 * c - qp * s; k0 = k0 * c - kp * s; }
    else        { q0 = q0 * c + qp * s; k0 = k0 * c + kp * s; }

    size_t o = win_addr(t, h, l);
    g_qw[o] = q0; g_qw[o + 32] = q1;
    g_kw[o] = k0; g_kw[o + 32] = k1;
}

// ---------------------------------------------------------------------------
// K4: windowed attention (fp32, __expf softmax)
// ---------------------------------------------------------------------------
#define QT(e, r) qT[(e) * 64 + (((r) + (e)) & 63)]

__global__ __launch_bounds__(64) void attn_kernel()
{
    __shared__ float qT[64 * 64];
    __shared__ float ks[64][64];
    __shared__ float vs[64][64];

    int b   = blockIdx.x;
    int w   = b & 255;
    int wwi = w & 15, whi = (w >> 4) & 15;
    bool left = (wwi == 0), top = (whi == 0);

    const float* qb = g_qw + (size_t)b * 4096;
    const float* kb = g_kw + (size_t)b * 4096;
    const float* vb = g_vw + (size_t)b * 4096;
    int tid = threadIdx.x;

    for (int i = tid; i < 1024; i += 64) {
        int r = i >> 4, c = (i & 15) << 2;
        float4 kv = *(const float4*)(kb + (i << 2));
        *(float4*)&ks[r][c] = kv;
        float4 vv = *(const float4*)(vb + (i << 2));
        *(float4*)&vs[r][c] = vv;
        float4 qv = *(const float4*)(qb + (i << 2));
        QT(c + 0, r) = qv.x; QT(c + 1, r) = qv.y;
        QT(c + 2, r) = qv.z; QT(c + 3, r) = qv.w;
    }
    __syncthreads();

    float sarr[64];
    #pragma unroll
    for (int k = 0; k < 64; k++) sarr[k] = 0.f;
    for (int e = 0; e < 64; e += 4) {
        float q0 = QT(e + 0, tid), q1 = QT(e + 1, tid);
        float q2 = QT(e + 2, tid), q3 = QT(e + 3, tid);
        #pragma unroll
        for (int k = 0; k < 64; k++) {
            float4 kv = *(const float4*)&ks[k][e];
            sarr[k] += q0 * kv.x + q1 * kv.y + q2 * kv.z + q3 * kv.w;
        }
    }

    int qh = tid >> 3, qw_ = tid & 7;
    bool qa = qh < SHIFT, ql = qw_ < SHIFT;
    float mx = -3.402823466e38f;
    #pragma unroll
    for (int k = 0; k < 64; k++) {
        int kh = k >> 3, kw = k & 7;
        bool ka = kh < SHIFT, kl = kw < SHIFT;
        bool m = (!left && !top)
               || (left && top && (ql == kl) && (qa == ka))
               || (left && !top && (ql == kl))
               || (!left && top && (qa == ka));
        if (!m) sarr[k] = -3.402823466e38f;
        mx = fmaxf(mx, sarr[k]);
    }
    float sum = 0.f;
    #pragma unroll
    for (int k = 0; k < 64; k++) {
        float p = __expf(sarr[k] - mx);
        sarr[k] = p;
        sum += p;
    }
    float inv = 1.0f / sum;

    float* ob = g_ow + (size_t)b * 4096 + (size_t)tid * 64;
    for (int e = 0; e < 64; e += 4) {
        float ax = 0.f, ay = 0.f, az = 0.f, aw = 0.f;
        #pragma unroll
        for (int k = 0; k < 64; k++) {
            float4 vv = *(const float4*)&vs[k][e];
            float p = sarr[k];
            ax += p * vv.x; ay += p * vv.y; az += p * vv.z; aw += p * vv.w;
        }
        float4 o4 = make_float4(ax * inv, ay * inv, az * inv, aw * inv);
        *(float4*)(ob + e) = o4;
    }
}

// ---------------------------------------------------------------------------
// K5: unwindow -> bf16 hi/lo
// ---------------------------------------------------------------------------
__global__ __launch_bounds__(256) void unwindow_kernel()
{
    int t = blockIdx.x;
    int n = t >> 14;
    int y = (t >> 7) & 127;
    int x = t & 127;
    int Y = (y + SHIFT) & 127, X = (x + SHIFT) & 127;
    int winbase = (Y >> 3) * 16 + (X >> 3);
    int spos = (Y & 7) * 8 + (X & 7);
    #pragma unroll
    for (int i = 0; i < 3; i++) {
        int c = threadIdx.x + 256 * i;
        int h = c >> 6, e = c & 63;
        size_t src = ((size_t)((n * NHEADS + h) * 256 + winbase)) * 4096
                   + (size_t)spos * 64 + e;
        split2(g_ow[src], &g_oi_hi[(size_t)t * DM + c], &g_oi_lo[(size_t)t * DM + c]);
    }
}

// ---------------------------------------------------------------------------
// host
// ---------------------------------------------------------------------------
static void launch_hgemm(const __nv_bfloat16* Ah, const __nv_bfloat16* Al,
                         const __nv_bfloat16* Bh, const __nv_bfloat16* Bl,
                         const float* D, float* C, int M, int N, int K,
                         int ldc, int mode)
{
    dim3 grid(N / 128, M / 128);
    hgemm_kernel<<<grid, 128, GEMM_SMEM>>>(Ah, Al, Bh, Bl, D, C, M, N, K, ldc, mode);
}

extern "C" void kernel_launch(void* const* d_in, const int* in_sizes, int n_in,
                              void* d_out, int out_size)
{
    const float* x          = (const float*)d_in[0];
    const float* pos        = (const float*)d_in[1];
    const float* cond       = (const float*)d_in[2];
    const float* ada1_w     = (const float*)d_in[3];
    const float* qkv_w      = (const float*)d_in[4];
    const float* attn_scale = (const float*)d_in[5];
    const float* rope_freqs = (const float*)d_in[6];
    const float* out_w      = (const float*)d_in[7];
    const float* ada2_w     = (const float*)d_in[8];
    const float* ff_up_w    = (const float*)d_in[9];
    const float* ff_down_w  = (const float*)d_in[10];
    float* out = (float*)d_out;

    cudaFuncSetAttribute(hgemm_kernel, cudaFuncAttributeMaxDynamicSharedMemorySize, GEMM_SMEM);

    float *p_scale1, *p_scale2, *p_qkv, *p_x2;
    __nv_bfloat16 *p_hh, *p_hl, *p_oih, *p_oil, *p_ah, *p_al, *p_wh, *p_wl;
    cudaGetSymbolAddress((void**)&p_scale1, g_scale1);
    cudaGetSymbolAddress((void**)&p_scale2, g_scale2);
    cudaGetSymbolAddress((void**)&p_qkv,    g_qkv);
    cudaGetSymbolAddress((void**)&p_x2,     g_x2);
    cudaGetSymbolAddress((void**)&p_hh,     g_h_hi);
    cudaGetSymbolAddress((void**)&p_hl,     g_h_lo);
    cudaGetSymbolAddress((void**)&p_oih,    g_oi_hi);
    cudaGetSymbolAddress((void**)&p_oil,    g_oi_lo);
    cudaGetSymbolAddress((void**)&p_ah,     g_a_hi);
    cudaGetSymbolAddress((void**)&p_al,     g_a_lo);
    cudaGetSymbolAddress((void**)&p_wh,     g_w_hi);
    cudaGetSymbolAddress((void**)&p_wl,     g_w_lo);

    const int OQKV = 0;
    const int OOUT = OQKV + W_QKV_SZ;
    const int OUP  = OOUT + W_OUT_SZ;
    const int ODN  = OUP + W_UP_SZ;

    wsplit_kernel<<<(W_QKV_SZ + 255) / 256, 256>>>(qkv_w,     p_wh + OQKV, p_wl + OQKV, W_QKV_SZ, DM, 0);
    wsplit_kernel<<<(W_OUT_SZ + 255) / 256, 256>>>(out_w,     p_wh + OOUT, p_wl + OOUT, W_OUT_SZ, DM, 0);
    wsplit_kernel<<<(W_UP_SZ  + 255) / 256, 256>>>(ff_up_w,   p_wh + OUP,  p_wl + OUP,  W_UP_SZ,  DM, 1);
    wsplit_kernel<<<(W_DN_SZ  + 255) / 256, 256>>>(ff_down_w, p_wh + ODN,  p_wl + ODN,  W_DN_SZ,  DFF, 0);

    ada_kernel<<<768, 256>>>(cond, ada1_w, ada2_w);
    rmsnorm_kernel<<<TOKENS, 256>>>(x, p_scale1);
    // qkv: q,k -> g_qkv (ldc=1536); v -> scatter to g_vw
    launch_hgemm(p_hh, p_hl, p_wh + OQKV, p_wl + OQKV, nullptr, p_qkv,
                 TOKENS, 3 * DM, DM, 2 * DM, 2);
    qk_transform_kernel<<<TOKENS, 384>>>(pos, attn_scale, rope_freqs);
    attn_kernel<<<NWIN, 64>>>();
    unwindow_kernel<<<TOKENS, 256>>>();
    launch_hgemm(p_oih, p_oil, p_wh + OOUT, p_wl + OOUT, x, p_x2,
                 TOKENS, DM, DM, DM, 0);
    rmsnorm_kernel<<<TOKENS, 256>>>(p_x2, p_scale2);
    // ff_up with fused gated GELU (interleaved weights) -> g_a_hi/lo
    launch_hgemm(p_hh, p_hl, p_wh + OUP, p_wl + OUP, nullptr, nullptr,
                 TOKENS, 2 * DFF, DM, 2 * DFF, 1);
    launch_hgemm(p_ah, p_al, p_wh + ODN, p_wl + ODN, p_x2, out,
                 TOKENS, DM, DFF, DM, 0);
}

// round 6
// speedup vs baseline: 1.0989x; 1.0989x over previous
#include <cuda_runtime.h>
#include <cuda_bf16.h>
#include <math.h>
#include <stdint.h>

// ---------------------------------------------------------------------------
// Problem constants
// ---------------------------------------------------------------------------
#define NBATCH   4
#define HDIM     128
#define WDIM     128
#define DM       768
#define NHEADS   12
#define DHEAD    64
#define DFF      2048
#define DC       768
#define WS       8
#define SHIFT    4
#define TOKENS   (NBATCH * HDIM * WDIM)          // 65536
#define NWIN     (NBATCH * NHEADS * 16 * 16)     // 12288
#define EPSV     1e-6f

// ---------------------------------------------------------------------------
// Scratch
// ---------------------------------------------------------------------------
#define W_QKV_SZ (3 * DM * DM)
#define W_OUT_SZ (DM * DM)
#define W_UP_SZ  (2 * DFF * DM)
#define W_DN_SZ  (DM * DFF)
#define W_TOTAL  (W_QKV_SZ + W_OUT_SZ + W_UP_SZ + W_DN_SZ)

__device__ float g_scale1[NBATCH * DM];
__device__ float g_scale2[NBATCH * DM];
__device__ float g_qkv [(size_t)TOKENS * 2 * DM];     // q,k (ldc=1536)
__device__ float g_vw  [(size_t)NWIN * 64 * 64];      // v, windowed (GEMM scatter)
__device__ float g_x2  [(size_t)TOKENS * DM];

__device__ __nv_bfloat16 g_h_hi [(size_t)TOKENS * DM];
__device__ __nv_bfloat16 g_h_lo [(size_t)TOKENS * DM];
__device__ __nv_bfloat16 g_oi_hi[(size_t)TOKENS * DM];
__device__ __nv_bfloat16 g_oi_lo[(size_t)TOKENS * DM];
__device__ __nv_bfloat16 g_a_hi [(size_t)TOKENS * DFF];
__device__ __nv_bfloat16 g_a_lo [(size_t)TOKENS * DFF];
__device__ __nv_bfloat16 g_w_hi [W_TOTAL];
__device__ __nv_bfloat16 g_w_lo [W_TOTAL];

__device__ __forceinline__ void split2(float v, __nv_bfloat16* hi, __nv_bfloat16* lo) {
    __nv_bfloat16 h = __float2bfloat16(v);
    *hi = h;
    *lo = __float2bfloat16(v - __bfloat162float(h));
}

// ---------------------------------------------------------------------------
// PTX helpers (sm_80+ features only; legal under compute_103)
// ---------------------------------------------------------------------------
__device__ __forceinline__ uint32_t smem_to_u32(const void* p) {
    uint32_t a;
    asm("{ .reg .u64 t; cvta.to.shared.u64 t, %1; cvt.u32.u64 %0, t; }" : "=r"(a) : "l"(p));
    return a;
}
#define CP_ASYNC16(sa, gp) \
    asm volatile("cp.async.cg.shared.global [%0], [%1], 16;" :: "r"(sa), "l"(gp))
#define CP_COMMIT() asm volatile("cp.async.commit_group;" ::: "memory")
#define CP_WAIT1()  asm volatile("cp.async.wait_group 1;" ::: "memory")
#define CP_WAIT0()  asm volatile("cp.async.wait_group 0;" ::: "memory")

__device__ __forceinline__ void ldsm_x4(uint32_t& r0, uint32_t& r1, uint32_t& r2,
                                        uint32_t& r3, uint32_t addr) {
    asm volatile("ldmatrix.sync.aligned.m8n8.x4.shared.b16 {%0,%1,%2,%3}, [%4];"
                 : "=r"(r0), "=r"(r1), "=r"(r2), "=r"(r3) : "r"(addr));
}
__device__ __forceinline__ void mma_bf16(float c[4], const uint32_t a[4],
                                         const uint32_t b[2]) {
    asm volatile("mma.sync.aligned.m16n8k16.row.col.f32.bf16.bf16.f32 "
                 "{%0,%1,%2,%3},{%4,%5,%6,%7},{%8,%9},{%0,%1,%2,%3};"
                 : "+f"(c[0]), "+f"(c[1]), "+f"(c[2]), "+f"(c[3])
                 : "r"(a[0]), "r"(a[1]), "r"(a[2]), "r"(a[3]),
                   "r"(b[0]), "r"(b[1]));
}

// window-scatter address helper (roll +4,+4 then 8x8 windows)
__device__ __forceinline__ size_t win_addr(int t, int h, int e) {
    int n = t >> 14;
    int y = (t >> 7) & 127;
    int x = t & 127;
    int Y = (y + SHIFT) & 127, X = (x + SHIFT) & 127;
    int wyx  = ((Y >> 3) << 4) + (X >> 3);
    int spos = ((Y & 7) << 3) + (X & 7);
    return ((size_t)((n * NHEADS + h) * 256 + wyx)) * 4096 + (size_t)spos * 64 + e;
}

// inverse: window b (n,h,wy,wx), slot r -> token index
__device__ __forceinline__ int win_token(int b, int r) {
    int n   = b / (NHEADS * 256);
    int rem = b % (NHEADS * 256);
    int w   = rem & 255;
    int Y = ((w >> 4) << 3) + (r >> 3);
    int X = ((w & 15) << 3) + (r & 7);
    int y = (Y - SHIFT) & 127, x = (X - SHIFT) & 127;
    return (n << 14) + (y << 7) + x;
}

// ---------------------------------------------------------------------------
// GEMM (R4 config): 128x128x32 tile, 8 warps (2m x 4n), warp tile 64x32.
// mode 0: C = (D?D:0) + A@B^T
// mode 1: fused gated-GELU -> g_a_hi/lo (weights pre-interleaved)
// mode 2: qkv: cols<1536 -> C (ldc=1536), cols>=1536 -> scatter V to g_vw
// ---------------------------------------------------------------------------
#define BKC     32
#define PADK    40
#define TILE_E  (128 * PADK)
#define STAGE_E (4 * TILE_E)
#define GEMM_SMEM (2 * STAGE_E * 2)

__global__ __launch_bounds__(256) void hgemm_kernel(
    const __nv_bfloat16* __restrict__ Ahi, const __nv_bfloat16* __restrict__ Alo,
    const __nv_bfloat16* __restrict__ Bhi, const __nv_bfloat16* __restrict__ Blo,
    const float* __restrict__ Dres, float* __restrict__ C,
    int M, int N, int K, int ldc, int mode)
{
    extern __shared__ __align__(128) char smem[];
    const uint32_t sbase = smem_to_u32(smem);
    const int tid = threadIdx.x, lane = tid & 31, wid = tid >> 5;
    const int wm = wid >> 2, wn = wid & 3;
    const size_t bm = (size_t)blockIdx.y * 128;
    const size_t bn = (size_t)blockIdx.x * 128;

    const __nv_bfloat16* gsrc[4] = { Ahi + bm * (size_t)K, Alo + bm * (size_t)K,
                                     Bhi + bn * (size_t)K, Blo + bn * (size_t)K };

    float acc[4][4][4];
    #pragma unroll
    for (int i = 0; i < 4; i++)
        #pragma unroll
        for (int j = 0; j < 4; j++)
            #pragma unroll
            for (int l = 0; l < 4; l++) acc[i][j][l] = 0.f;

    const int row_l = tid >> 2, seg_l = tid & 3;
    const int nstage = K / BKC;

    auto issue = [&](int st) {
        const int k0 = st * BKC;
        const uint32_t sb = sbase + (uint32_t)((st & 1) * STAGE_E * 2);
        #pragma unroll
        for (int m_ = 0; m_ < 4; m_++) {
            #pragma unroll
            for (int j = 0; j < 2; j++) {
                int row = row_l + j * 64;
                const __nv_bfloat16* gp = gsrc[m_] + (size_t)row * K + k0 + seg_l * 8;
                uint32_t sa = sb + (uint32_t)((m_ * TILE_E + row * PADK + seg_l * 8) * 2);
                CP_ASYNC16(sa, gp);
            }
        }
        CP_COMMIT();
    };

    issue(0);
    if (nstage > 1) issue(1);

    const int a_r = lane & 15, a_h = (lane >> 4) << 3;
    const int b_r = (lane & 7) + ((lane & 16) >> 1);
    const int b_k = lane & 8;

    for (int st = 0; st < nstage; st++) {
        if (st + 1 < nstage) { CP_WAIT1(); } else { CP_WAIT0(); }
        __syncthreads();

        const uint32_t sb = sbase + (uint32_t)((st & 1) * STAGE_E * 2);
        const uint32_t sAhi = sb;
        const uint32_t sAlo = sb + TILE_E * 2;
        const uint32_t sBhi = sb + 2 * TILE_E * 2;
        const uint32_t sBlo = sb + 3 * TILE_E * 2;

        #pragma unroll
        for (int kk = 0; kk < BKC; kk += 16) {
            uint32_t a[4][4], al[4][4], bh[4][2], bl[4][2];
            #pragma unroll
            for (int mt = 0; mt < 4; mt++)
                ldsm_x4(a[mt][0], a[mt][1], a[mt][2], a[mt][3],
                        sAhi + (uint32_t)(((wm * 64 + mt * 16 + a_r) * PADK + kk + a_h) * 2));
            #pragma unroll
            for (int p = 0; p < 2; p++) {
                uint32_t r0, r1, r2, r3;
                ldsm_x4(r0, r1, r2, r3,
                        sBhi + (uint32_t)(((wn * 32 + p * 16 + b_r) * PADK + kk + b_k) * 2));
                bh[p * 2][0] = r0; bh[p * 2][1] = r1;
                bh[p * 2 + 1][0] = r2; bh[p * 2 + 1][1] = r3;
            }
            #pragma unroll
            for (int mt = 0; mt < 4; mt++)
                #pragma unroll
                for (int nt = 0; nt < 4; nt++)
                    mma_bf16(acc[mt][nt], a[mt], bh[nt]);
            #pragma unroll
            for (int p = 0; p < 2; p++) {
                uint32_t r0, r1, r2, r3;
                ldsm_x4(r0, r1, r2, r3,
                        sBlo + (uint32_t)(((wn * 32 + p * 16 + b_r) * PADK + kk + b_k) * 2));
                bl[p * 2][0] = r0; bl[p * 2][1] = r1;
                bl[p * 2 + 1][0] = r2; bl[p * 2 + 1][1] = r3;
            }
            #pragma unroll
            for (int mt = 0; mt < 4; mt++)
                #pragma unroll
                for (int nt = 0; nt < 4; nt++)
                    mma_bf16(acc[mt][nt], a[mt], bl[nt]);
            #pragma unroll
            for (int mt = 0; mt < 4; mt++)
                ldsm_x4(al[mt][0], al[mt][1], al[mt][2], al[mt][3],
                        sAlo + (uint32_t)(((wm * 64 + mt * 16 + a_r) * PADK + kk + a_h) * 2));
            #pragma unroll
            for (int mt = 0; mt < 4; mt++)
                #pragma unroll
                for (int nt = 0; nt < 4; nt++)
                    mma_bf16(acc[mt][nt], al[mt], bh[nt]);
        }
        __syncthreads();
        if (st + 2 < nstage) issue(st + 2);
    }

    const int er = lane >> 2, ec = (lane & 3) * 2;

    if (mode == 1) {
        #pragma unroll
        for (int mt = 0; mt < 4; mt++) {
            size_t r0 = bm + wm * 64 + mt * 16 + er;
            size_t r1 = r0 + 8;
            #pragma unroll
            for (int nt = 0; nt < 4; nt++) {
                int col = (int)bn + wn * 32 + nt * 8 + ec;
                int j = col >> 1;
                float a0 = acc[mt][nt][0], gg0 = acc[mt][nt][1];
                float a1 = acc[mt][nt][2], gg1 = acc[mt][nt][3];
                float v0 = a0 * (gg0 * 0.5f * (1.0f + erff(gg0 * 0.70710678118654752f)));
                float v1 = a1 * (gg1 * 0.5f * (1.0f + erff(gg1 * 0.70710678118654752f)));
                split2(v0, &g_a_hi[r0 * DFF + j], &g_a_lo[r0 * DFF + j]);
                split2(v1, &g_a_hi[r1 * DFF + j], &g_a_lo[r1 * DFF + j]);
            }
        }
        return;
    }

    if (mode == 2 && bn >= 1536) {
        #pragma unroll
        for (int mt = 0; mt < 4; mt++) {
            int t0 = (int)bm + wm * 64 + mt * 16 + er;
            int t1 = t0 + 8;
            #pragma unroll
            for (int nt = 0; nt < 4; nt++) {
                int col = (int)bn + wn * 32 + nt * 8 + ec;
                int h = (col - 1536) >> 6;
                int e = col & 63;
                float2 v0 = make_float2(acc[mt][nt][0], acc[mt][nt][1]);
                float2 v1 = make_float2(acc[mt][nt][2], acc[mt][nt][3]);
                *(float2*)&g_vw[win_addr(t0, h, e)] = v0;
                *(float2*)&g_vw[win_addr(t1, h, e)] = v1;
            }
        }
        return;
    }

    #pragma unroll
    for (int mt = 0; mt < 4; mt++) {
        size_t row0 = bm + wm * 64 + mt * 16 + er;
        #pragma unroll
        for (int nt = 0; nt < 4; nt++) {
            size_t col = bn + wn * 32 + nt * 8 + ec;
            float* p0 = C + row0 * (size_t)ldc + col;
            float* p1 = C + (row0 + 8) * (size_t)ldc + col;
            float2 v0 = make_float2(acc[mt][nt][0], acc[mt][nt][1]);
            float2 v1 = make_float2(acc[mt][nt][2], acc[mt][nt][3]);
            if (Dres) {
                const float2 d0 = *(const float2*)(Dres + row0 * (size_t)ldc + col);
                const float2 d1 = *(const float2*)(Dres + (row0 + 8) * (size_t)ldc + col);
                v0.x += d0.x; v0.y += d0.y; v1.x += d1.x; v1.y += d1.y;
            }
            *(float2*)p0 = v0;
            *(float2*)p1 = v1;
        }
    }
}

// ---------------------------------------------------------------------------
// K0: ada scales
// ---------------------------------------------------------------------------
__global__ void ada_kernel(const float* __restrict__ cond,
                           const float* __restrict__ w1,
                           const float* __restrict__ w2)
{
    int gw   = (blockIdx.x * blockDim.x + threadIdx.x) >> 5;
    int lane = threadIdx.x & 31;
    if (gw >= 2 * NBATCH * DM) return;
    int which = gw / (NBATCH * DM);
    int rem   = gw % (NBATCH * DM);
    int n = rem / DM, d = rem % DM;
    const float* w  = which ? w2 : w1;
    const float* cr = cond + n * DC;
    const float* wr = w + (size_t)d * DC;
    float s = 0.f;
    for (int i = lane; i < DC; i += 32) s += cr[i] * wr[i];
    #pragma unroll
    for (int o = 16; o; o >>= 1) s += __shfl_xor_sync(0xffffffffu, s, o);
    if (lane == 0) (which ? g_scale2 : g_scale1)[rem] = s + 1.0f;
}

// ---------------------------------------------------------------------------
// K1: RMSNorm * ada -> bf16 hi/lo
// ---------------------------------------------------------------------------
__global__ __launch_bounds__(256) void rmsnorm_kernel(const float* __restrict__ x,
                                                      const float* __restrict__ scale)
{
    int t = blockIdx.x;
    int n = t >> 14;
    const float* xr = x + (size_t)t * DM;
    float v[3]; float ss = 0.f;
    #pragma unroll
    for (int i = 0; i < 3; i++) { v[i] = xr[threadIdx.x + 256 * i]; ss += v[i] * v[i]; }
    __shared__ float red[8];
    #pragma unroll
    for (int o = 16; o; o >>= 1) ss += __shfl_xor_sync(0xffffffffu, ss, o);
    if ((threadIdx.x & 31) == 0) red[threadIdx.x >> 5] = ss;
    __syncthreads();
    if (threadIdx.x == 0) {
        float r = 0.f;
        #pragma unroll
        for (int i = 0; i < 8; i++) r += red[i];
        red[0] = r;
    }
    __syncthreads();
    float inv = rsqrtf(red[0] * (1.0f / DM) + EPSV);
    const float* sc = scale + (size_t)n * DM;
    #pragma unroll
    for (int i = 0; i < 3; i++) {
        int c = threadIdx.x + 256 * i;
        float o = v[i] * sc[c] * inv;
        split2(o, &g_h_hi[(size_t)t * DM + c], &g_h_lo[(size_t)t * DM + c]);
    }
}

// ---------------------------------------------------------------------------
// K2: weight split (optional row interleave for ff_up gating)
// ---------------------------------------------------------------------------
__global__ __launch_bounds__(256) void wsplit_kernel(const float* __restrict__ w,
                                                     __nv_bfloat16* __restrict__ hi,
                                                     __nv_bfloat16* __restrict__ lo,
                                                     int n, int rowlen, int perm)
{
    int i = blockIdx.x * 256 + threadIdx.x;
    if (i >= n) return;
    int dst = i;
    if (perm) {
        int r = i / rowlen, c = i % rowlen;
        int dr = (r < DFF) ? (2 * r) : (2 * (r - DFF) + 1);
        dst = dr * rowlen + c;
    }
    split2(w[i], &hi[dst], &lo[dst]);
}

// ---------------------------------------------------------------------------
// K3: fused attention: gather q,k from g_qkv, L2-norm + RoPE in-block,
// scores+softmax+PV, write o as bf16 hi/lo directly to g_oi (unwindowed).
// One block (64 threads) per window-head. smem = 51200 B.
// qR/kR rows padded to 68 floats; vs rows 64.
// ---------------------------------------------------------------------------
#define ATT_PAD  68
#define ATT_SMEM (2 * 64 * ATT_PAD * 4 + 64 * 64 * 4)   // 51200

__global__ __launch_bounds__(64) void attn_kernel(const float* __restrict__ pos,
                                                  const float* __restrict__ attn_scale,
                                                  const float* __restrict__ rope_freqs)
{
    extern __shared__ __align__(16) float sm[];
    float* qR = sm;
    float* kR = sm + 64 * ATT_PAD;
    float* vs = sm + 2 * 64 * ATT_PAD;

    const int b   = blockIdx.x;
    const int rem = b % (NHEADS * 256);
    const int h   = rem >> 8;
    const int w   = rem & 255;
    const bool left = ((w & 15) == 0), top = ((w >> 4) == 0);
    const int tid = threadIdx.x;

    // cooperative gather: q,k rows from g_qkv (token map), v from g_vw
    const float* vb = g_vw + (size_t)b * 4096;
    #pragma unroll
    for (int i = tid; i < 1024; i += 64) {
        int r = i >> 4, c4 = (i & 15) << 2;
        int t = win_token(b, r);
        const float* qk = g_qkv + (size_t)t * (2 * DM) + h * DHEAD + c4;
        float4 qv = *(const float4*)qk;
        float4 kv = *(const float4*)(qk + DM);
        float4 vv = *(const float4*)(vb + (i << 2));
        *(float4*)(qR + r * ATT_PAD + c4) = qv;
        *(float4*)(kR + r * ATT_PAD + c4) = kv;
        *(float4*)(vs + r * 64 + c4)      = vv;
    }
    __syncthreads();

    // per-row transform: L2-norm * sqrt(scale) + RoPE (own row, in place)
    {
        float* qrow = qR + tid * ATT_PAD;
        float* krow = kR + tid * ATT_PAD;
        float sq = 0.f, sk = 0.f;
        #pragma unroll
        for (int e = 0; e < 64; e++) { float a = qrow[e], c = krow[e]; sq += a * a; sk += c * c; }
        float ssh = sqrtf(attn_scale[h]);
        float rq = ssh * rsqrtf(sq + EPSV);
        float rk = ssh * rsqrtf(sk + EPSV);

        int t = win_token(b, tid);
        float p0 = pos[(size_t)t * 2 + 0];
        float p1 = pos[(size_t)t * 2 + 1];
        #pragma unroll
        for (int e = 0; e < 16; e++) {
            float freq = rope_freqs[h * 8 + (e & 7)];
            float th = (e < 8 ? p0 : p1) * freq;
            float c = cosf(th), s = sinf(th);
            float q1 = qrow[e] * rq, q2 = qrow[e + 16] * rq;
            float k1 = krow[e] * rk, k2 = krow[e + 16] * rk;
            qrow[e]      = q1 * c - q2 * s;
            qrow[e + 16] = q2 * c + q1 * s;
            krow[e]      = k1 * c - k2 * s;
            krow[e + 16] = k2 * c + k1 * s;
        }
        #pragma unroll
        for (int e = 32; e < 64; e++) { qrow[e] *= rq; krow[e] *= rk; }
    }
    __syncthreads();

    // scores: query = tid (own qR row; kR rows broadcast)
    float sarr[64];
    #pragma unroll
    for (int k = 0; k < 64; k++) sarr[k] = 0.f;
    const float* qrow = qR + tid * ATT_PAD;
    for (int e = 0; e < 64; e += 4) {
        float q0 = qrow[e], q1 = qrow[e + 1], q2 = qrow[e + 2], q3 = qrow[e + 3];
        #pragma unroll
        for (int k = 0; k < 64; k++) {
            float4 kv = *(const float4*)(kR + k * ATT_PAD + e);
            sarr[k] += q0 * kv.x + q1 * kv.y + q2 * kv.z + q3 * kv.w;
        }
    }

    // mask + softmax
    int qh = tid >> 3, qw_ = tid & 7;
    bool qa = qh < SHIFT, ql = qw_ < SHIFT;
    float mx = -3.402823466e38f;
    #pragma unroll
    for (int k = 0; k < 64; k++) {
        int kh = k >> 3, kw = k & 7;
        bool ka = kh < SHIFT, kl = kw < SHIFT;
        bool m = (!left && !top)
               || (left && top && (ql == kl) && (qa == ka))
               || (left && !top && (ql == kl))
               || (!left && top && (qa == ka));
        if (!m) sarr[k] = -3.402823466e38f;
        mx = fmaxf(mx, sarr[k]);
    }
    float sum = 0.f;
    #pragma unroll
    for (int k = 0; k < 64; k++) {
        float p = __expf(sarr[k] - mx);
        sarr[k] = p;
        sum += p;
    }
    float inv = 1.0f / sum;

    // PV: write o into own qR row (float), then cooperative bf16 split store
    float* orow = qR + tid * ATT_PAD;
    for (int e = 0; e < 64; e += 4) {
        float ax = 0.f, ay = 0.f, az = 0.f, aw = 0.f;
        #pragma unroll
        for (int k = 0; k < 64; k++) {
            float4 vv = *(const float4*)(vs + k * 64 + e);
            float p = sarr[k];
            ax += p * vv.x; ay += p * vv.y; az += p * vv.z; aw += p * vv.w;
        }
        orow[e] = ax * inv; orow[e + 1] = ay * inv;
        orow[e + 2] = az * inv; orow[e + 3] = aw * inv;
    }
    __syncthreads();

    // coalesced unwindowed store: 16 threads per row, 4 elems each
    #pragma unroll
    for (int i = tid; i < 1024; i += 64) {
        int r = i >> 4, c4 = (i & 15) << 2;
        int t = win_token(b, r);
        size_t dst = (size_t)t * DM + h * DHEAD + c4;
        const float* src = qR + r * ATT_PAD + c4;
        __nv_bfloat16 hi4[4], lo4[4];
        #pragma unroll
        for (int j = 0; j < 4; j++) split2(src[j], &hi4[j], &lo4[j]);
        *(uint2*)&g_oi_hi[dst] = *(uint2*)hi4;
        *(uint2*)&g_oi_lo[dst] = *(uint2*)lo4;
    }
}

// ---------------------------------------------------------------------------
// host
// ---------------------------------------------------------------------------
static void launch_hgemm(const __nv_bfloat16* Ah, const __nv_bfloat16* Al,
                         const __nv_bfloat16* Bh, const __nv_bfloat16* Bl,
                         const float* D, float* C, int M, int N, int K,
                         int ldc, int mode)
{
    dim3 grid(N / 128, M / 128);
    hgemm_kernel<<<grid, 256, GEMM_SMEM>>>(Ah, Al, Bh, Bl, D, C, M, N, K, ldc, mode);
}

extern "C" void kernel_launch(void* const* d_in, const int* in_sizes, int n_in,
                              void* d_out, int out_size)
{
    const float* x          = (const float*)d_in[0];
    const float* pos        = (const float*)d_in[1];
    const float* cond       = (const float*)d_in[2];
    const float* ada1_w     = (const float*)d_in[3];
    const float* qkv_w      = (const float*)d_in[4];
    const float* attn_scale = (const float*)d_in[5];
    const float* rope_freqs = (const float*)d_in[6];
    const float* out_w      = (const float*)d_in[7];
    const float* ada2_w     = (const float*)d_in[8];
    const float* ff_up_w    = (const float*)d_in[9];
    const float* ff_down_w  = (const float*)d_in[10];
    float* out = (float*)d_out;

    cudaFuncSetAttribute(hgemm_kernel, cudaFuncAttributeMaxDynamicSharedMemorySize, GEMM_SMEM);
    cudaFuncSetAttribute(attn_kernel, cudaFuncAttributeMaxDynamicSharedMemorySize, ATT_SMEM);

    float *p_scale1, *p_scale2, *p_qkv, *p_x2;
    __nv_bfloat16 *p_hh, *p_hl, *p_oih, *p_oil, *p_ah, *p_al, *p_wh, *p_wl;
    cudaGetSymbolAddress((void**)&p_scale1, g_scale1);
    cudaGetSymbolAddress((void**)&p_scale2, g_scale2);
    cudaGetSymbolAddress((void**)&p_qkv,    g_qkv);
    cudaGetSymbolAddress((void**)&p_x2,     g_x2);
    cudaGetSymbolAddress((void**)&p_hh,     g_h_hi);
    cudaGetSymbolAddress((void**)&p_hl,     g_h_lo);
    cudaGetSymbolAddress((void**)&p_oih,    g_oi_hi);
    cudaGetSymbolAddress((void**)&p_oil,    g_oi_lo);
    cudaGetSymbolAddress((void**)&p_ah,     g_a_hi);
    cudaGetSymbolAddress((void**)&p_al,     g_a_lo);
    cudaGetSymbolAddress((void**)&p_wh,     g_w_hi);
    cudaGetSymbolAddress((void**)&p_wl,     g_w_lo);

    const int OQKV = 0;
    const int OOUT = OQKV + W_QKV_SZ;
    const int OUP  = OOUT + W_OUT_SZ;
    const int ODN  = OUP + W_UP_SZ;

    wsplit_kernel<<<(W_QKV_SZ + 255) / 256, 256>>>(qkv_w,     p_wh + OQKV, p_wl + OQKV, W_QKV_SZ, DM, 0);
    wsplit_kernel<<<(W_OUT_SZ + 255) / 256, 256>>>(out_w,     p_wh + OOUT, p_wl + OOUT, W_OUT_SZ, DM, 0);
    wsplit_kernel<<<(W_UP_SZ  + 255) / 256, 256>>>(ff_up_w,   p_wh + OUP,  p_wl + OUP,  W_UP_SZ,  DM, 1);
    wsplit_kernel<<<(W_DN_SZ  + 255) / 256, 256>>>(ff_down_w, p_wh + ODN,  p_wl + ODN,  W_DN_SZ,  DFF, 0);

    ada_kernel<<<768, 256>>>(cond, ada1_w, ada2_w);
    rmsnorm_kernel<<<TOKENS, 256>>>(x, p_scale1);
    // qkv: q,k -> g_qkv (ldc=1536); v -> scatter to g_vw
    launch_hgemm(p_hh, p_hl, p_wh + OQKV, p_wl + OQKV, nullptr, p_qkv,
                 TOKENS, 3 * DM, DM, 2 * DM, 2);
    // fused qk-transform + attention + unwindow
    attn_kernel<<<NWIN, 64, ATT_SMEM>>>(pos, attn_scale, rope_freqs);
    launch_hgemm(p_oih, p_oil, p_wh + OOUT, p_wl + OOUT, x, p_x2,
                 TOKENS, DM, DM, DM, 0);
    rmsnorm_kernel<<<TOKENS, 256>>>(p_x2, p_scale2);
    launch_hgemm(p_hh, p_hl, p_wh + OUP, p_wl + OUP, nullptr, nullptr,
                 TOKENS, 2 * DFF, DM, 2 * DFF, 1);
    launch_hgemm(p_ah, p_al, p_wh + ODN, p_wl + ODN, p_x2, out,
                 TOKENS, DM, DFF, DM, 0);
}

// round 7
// speedup vs baseline: 1.3517x; 1.2301x over previous
#include <cuda_runtime.h>
#include <cuda_bf16.h>
#include <cuda_fp16.h>
#include <math.h>
#include <stdint.h>

// ---------------------------------------------------------------------------
// Problem constants
// ---------------------------------------------------------------------------
#define NBATCH   4
#define HDIM     128
#define WDIM     128
#define DM       768
#define NHEADS   12
#define DHEAD    64
#define DFF      2048
#define DC       768
#define WS       8
#define SHIFT    4
#define TOKENS   (NBATCH * HDIM * WDIM)          // 65536
#define NWIN     (NBATCH * NHEADS * 16 * 16)     // 12288
#define EPSV     1e-6f

// ---------------------------------------------------------------------------
// Scratch
// ---------------------------------------------------------------------------
#define W_QKV_SZ (3 * DM * DM)
#define W_OUT_SZ (DM * DM)
#define W_UP_SZ  (2 * DFF * DM)
#define W_DN_SZ  (DM * DFF)
#define W_TOTAL  (W_QKV_SZ + W_OUT_SZ + W_UP_SZ + W_DN_SZ)

__device__ float g_scale1[NBATCH * DM];
__device__ float g_scale2[NBATCH * DM];
__device__ float g_qkv [(size_t)TOKENS * 2 * DM];     // q,k fp32 (ldc=1536)
__device__ float g_vw  [(size_t)NWIN * 64 * 64];      // v windowed fp32
__device__ float g_x2  [(size_t)TOKENS * DM];

__device__ __half g_h  [(size_t)TOKENS * DM];         // activations (single fp16)
__device__ __half g_oi [(size_t)TOKENS * DM];
__device__ __half g_a  [(size_t)TOKENS * DFF];
__device__ __half g_w_hi[W_TOTAL];                    // weights split fp16 hi/lo
__device__ __half g_w_lo[W_TOTAL];

__device__ __forceinline__ void wsplit2(float v, __half* hi, __half* lo) {
    __half h = __float2half(v);
    *hi = h;
    *lo = __float2half(v - __half2float(h));
}

// ---------------------------------------------------------------------------
// PTX helpers (sm_80+ features only; legal under compute_103)
// ---------------------------------------------------------------------------
__device__ __forceinline__ uint32_t smem_to_u32(const void* p) {
    uint32_t a;
    asm("{ .reg .u64 t; cvta.to.shared.u64 t, %1; cvt.u32.u64 %0, t; }" : "=r"(a) : "l"(p));
    return a;
}
#define CP_ASYNC16(sa, gp) \
    asm volatile("cp.async.cg.shared.global [%0], [%1], 16;" :: "r"(sa), "l"(gp))
#define CP_COMMIT() asm volatile("cp.async.commit_group;" ::: "memory")
#define CP_WAIT1()  asm volatile("cp.async.wait_group 1;" ::: "memory")
#define CP_WAIT0()  asm volatile("cp.async.wait_group 0;" ::: "memory")

__device__ __forceinline__ void ldsm_x4(uint32_t& r0, uint32_t& r1, uint32_t& r2,
                                        uint32_t& r3, uint32_t addr) {
    asm volatile("ldmatrix.sync.aligned.m8n8.x4.shared.b16 {%0,%1,%2,%3}, [%4];"
                 : "=r"(r0), "=r"(r1), "=r"(r2), "=r"(r3) : "r"(addr));
}
__device__ __forceinline__ void mma_f16(float c[4], const uint32_t a[4],
                                        const uint32_t b[2]) {
    asm volatile("mma.sync.aligned.m16n8k16.row.col.f32.f16.f16.f32 "
                 "{%0,%1,%2,%3},{%4,%5,%6,%7},{%8,%9},{%0,%1,%2,%3};"
                 : "+f"(c[0]), "+f"(c[1]), "+f"(c[2]), "+f"(c[3])
                 : "r"(a[0]), "r"(a[1]), "r"(a[2]), "r"(a[3]),
                   "r"(b[0]), "r"(b[1]));
}

// window-scatter address helper (roll +4,+4 then 8x8 windows)
__device__ __forceinline__ size_t win_addr(int t, int h, int e) {
    int n = t >> 14;
    int y = (t >> 7) & 127;
    int x = t & 127;
    int Y = (y + SHIFT) & 127, X = (x + SHIFT) & 127;
    int wyx  = ((Y >> 3) << 4) + (X >> 3);
    int spos = ((Y & 7) << 3) + (X & 7);
    return ((size_t)((n * NHEADS + h) * 256 + wyx)) * 4096 + (size_t)spos * 64 + e;
}

// inverse: window b, slot r -> token index
__device__ __forceinline__ int win_token(int b, int r) {
    int n   = b / (NHEADS * 256);
    int rem = b % (NHEADS * 256);
    int w   = rem & 255;
    int Y = ((w >> 4) << 3) + (r >> 3);
    int X = ((w & 15) << 3) + (r & 7);
    int y = (Y - SHIFT) & 127, x = (X - SHIFT) & 127;
    return (n << 14) + (y << 7) + x;
}

// ---------------------------------------------------------------------------
// GEMM: C = (D?D:0) + A @ (Bhi+Blo)^T.  A fp16 single, weights fp16 hi/lo.
// 128x128x32 tile, 8 warps (2m x 4n), warp tile 64x32, fp16 x2.
// mode 0: plain (+residual)   mode 1: fused gated-GELU -> g_a
// mode 2: qkv (cols<1536 -> C fp32; cols>=1536 -> scatter V to g_vw)
// ---------------------------------------------------------------------------
#define BKC     32
#define PADK    40
#define TILE_E  (128 * PADK)
#define STAGE_E (3 * TILE_E)
#define GEMM_SMEM (2 * STAGE_E * 2)     // 61440 bytes

__global__ __launch_bounds__(256, 2) void hgemm_kernel(
    const __half* __restrict__ A,
    const __half* __restrict__ Bhi, const __half* __restrict__ Blo,
    const float* __restrict__ Dres, float* __restrict__ C,
    int M, int N, int K, int ldc, int mode)
{
    extern __shared__ __align__(128) char smem[];
    const uint32_t sbase = smem_to_u32(smem);
    const int tid = threadIdx.x, lane = tid & 31, wid = tid >> 5;
    const int wm = wid >> 2, wn = wid & 3;
    const size_t bm = (size_t)blockIdx.y * 128;
    const size_t bn = (size_t)blockIdx.x * 128;

    const __half* gsrc[3] = { A + bm * (size_t)K, Bhi + bn * (size_t)K,
                              Blo + bn * (size_t)K };

    float acc[4][4][4];
    #pragma unroll
    for (int i = 0; i < 4; i++)
        #pragma unroll
        for (int j = 0; j < 4; j++)
            #pragma unroll
            for (int l = 0; l < 4; l++) acc[i][j][l] = 0.f;

    const int row_l = tid >> 1, seg_l = (tid & 1) << 1;   // 2 segs per thread pair
    const int nstage = K / BKC;

    // 512 16B-chunks per matrix per stage (128 rows x 4 chunks); 256 threads
    auto issue = [&](int st) {
        const int k0 = st * BKC;
        const uint32_t sb = sbase + (uint32_t)((st & 1) * STAGE_E * 2);
        #pragma unroll
        for (int m_ = 0; m_ < 3; m_++) {
            #pragma unroll
            for (int j = 0; j < 2; j++) {
                int row = row_l;
                int seg = seg_l + j;                      // 0..3
                const __half* gp = gsrc[m_] + (size_t)row * K + k0 + seg * 8;
                uint32_t sa = sb + (uint32_t)((m_ * TILE_E + row * PADK + seg * 8) * 2);
                CP_ASYNC16(sa, gp);
            }
        }
        CP_COMMIT();
    };

    issue(0);
    if (nstage > 1) issue(1);

    const int a_r = lane & 15, a_h = (lane >> 4) << 3;
    const int b_r = (lane & 7) + ((lane & 16) >> 1);
    const int b_k = lane & 8;

    for (int st = 0; st < nstage; st++) {
        if (st + 1 < nstage) { CP_WAIT1(); } else { CP_WAIT0(); }
        __syncthreads();

        const uint32_t sb = sbase + (uint32_t)((st & 1) * STAGE_E * 2);
        const uint32_t sA   = sb;
        const uint32_t sBhi = sb + TILE_E * 2;
        const uint32_t sBlo = sb + 2 * TILE_E * 2;

        #pragma unroll
        for (int kk = 0; kk < BKC; kk += 16) {
            uint32_t a[4][4], bh[4][2], bl[4][2];
            #pragma unroll
            for (int mt = 0; mt < 4; mt++)
                ldsm_x4(a[mt][0], a[mt][1], a[mt][2], a[mt][3],
                        sA + (uint32_t)(((wm * 64 + mt * 16 + a_r) * PADK + kk + a_h) * 2));
            #pragma unroll
            for (int p = 0; p < 2; p++) {
                uint32_t r0, r1, r2, r3;
                ldsm_x4(r0, r1, r2, r3,
                        sBhi + (uint32_t)(((wn * 32 + p * 16 + b_r) * PADK + kk + b_k) * 2));
                bh[p * 2][0] = r0; bh[p * 2][1] = r1;
                bh[p * 2 + 1][0] = r2; bh[p * 2 + 1][1] = r3;
            }
            #pragma unroll
            for (int mt = 0; mt < 4; mt++)
                #pragma unroll
                for (int nt = 0; nt < 4; nt++)
                    mma_f16(acc[mt][nt], a[mt], bh[nt]);
            #pragma unroll
            for (int p = 0; p < 2; p++) {
                uint32_t r0, r1, r2, r3;
                ldsm_x4(r0, r1, r2, r3,
                        sBlo + (uint32_t)(((wn * 32 + p * 16 + b_r) * PADK + kk + b_k) * 2));
                bl[p * 2][0] = r0; bl[p * 2][1] = r1;
                bl[p * 2 + 1][0] = r2; bl[p * 2 + 1][1] = r3;
            }
            #pragma unroll
            for (int mt = 0; mt < 4; mt++)
                #pragma unroll
                for (int nt = 0; nt < 4; nt++)
                    mma_f16(acc[mt][nt], a[mt], bl[nt]);
        }
        __syncthreads();
        if (st + 2 < nstage) issue(st + 2);
    }

    const int er = lane >> 2, ec = (lane & 3) * 2;

    if (mode == 1) {
        // fused gated GELU: col pair (even,odd) = (a_j, g_j); j = col/2
        #pragma unroll
        for (int mt = 0; mt < 4; mt++) {
            size_t r0 = bm + wm * 64 + mt * 16 + er;
            size_t r1 = r0 + 8;
            #pragma unroll
            for (int nt = 0; nt < 4; nt++) {
                int col = (int)bn + wn * 32 + nt * 8 + ec;
                int j = col >> 1;
                float a0 = acc[mt][nt][0], gg0 = acc[mt][nt][1];
                float a1 = acc[mt][nt][2], gg1 = acc[mt][nt][3];
                float v0 = a0 * (gg0 * 0.5f * (1.0f + erff(gg0 * 0.70710678118654752f)));
                float v1 = a1 * (gg1 * 0.5f * (1.0f + erff(gg1 * 0.70710678118654752f)));
                g_a[r0 * DFF + j] = __float2half(v0);
                g_a[r1 * DFF + j] = __float2half(v1);
            }
        }
        return;
    }

    if (mode == 2 && bn >= 1536) {
        #pragma unroll
        for (int mt = 0; mt < 4; mt++) {
            int t0 = (int)bm + wm * 64 + mt * 16 + er;
            int t1 = t0 + 8;
            #pragma unroll
            for (int nt = 0; nt < 4; nt++) {
                int col = (int)bn + wn * 32 + nt * 8 + ec;
                int h = (col - 1536) >> 6;
                int e = col & 63;
                float2 v0 = make_float2(acc[mt][nt][0], acc[mt][nt][1]);
                float2 v1 = make_float2(acc[mt][nt][2], acc[mt][nt][3]);
                *(float2*)&g_vw[win_addr(t0, h, e)] = v0;
                *(float2*)&g_vw[win_addr(t1, h, e)] = v1;
            }
        }
        return;
    }

    #pragma unroll
    for (int mt = 0; mt < 4; mt++) {
        size_t row0 = bm + wm * 64 + mt * 16 + er;
        #pragma unroll
        for (int nt = 0; nt < 4; nt++) {
            size_t col = bn + wn * 32 + nt * 8 + ec;
            float* p0 = C + row0 * (size_t)ldc + col;
            float* p1 = C + (row0 + 8) * (size_t)ldc + col;
            float2 v0 = make_float2(acc[mt][nt][0], acc[mt][nt][1]);
            float2 v1 = make_float2(acc[mt][nt][2], acc[mt][nt][3]);
            if (Dres) {
                const float2 d0 = *(const float2*)(Dres + row0 * (size_t)ldc + col);
                const float2 d1 = *(const float2*)(Dres + (row0 + 8) * (size_t)ldc + col);
                v0.x += d0.x; v0.y += d0.y; v1.x += d1.x; v1.y += d1.y;
            }
            *(float2*)p0 = v0;
            *(float2*)p1 = v1;
        }
    }
}

// ---------------------------------------------------------------------------
// K0: ada scales
// ---------------------------------------------------------------------------
__global__ void ada_kernel(const float* __restrict__ cond,
                           const float* __restrict__ w1,
                           const float* __restrict__ w2)
{
    int gw   = (blockIdx.x * blockDim.x + threadIdx.x) >> 5;
    int lane = threadIdx.x & 31;
    if (gw >= 2 * NBATCH * DM) return;
    int which = gw / (NBATCH * DM);
    int rem   = gw % (NBATCH * DM);
    int n = rem / DM, d = rem % DM;
    const float* w  = which ? w2 : w1;
    const float* cr = cond + n * DC;
    const float* wr = w + (size_t)d * DC;
    float s = 0.f;
    for (int i = lane; i < DC; i += 32) s += cr[i] * wr[i];
    #pragma unroll
    for (int o = 16; o; o >>= 1) s += __shfl_xor_sync(0xffffffffu, s, o);
    if (lane == 0) (which ? g_scale2 : g_scale1)[rem] = s + 1.0f;
}

// ---------------------------------------------------------------------------
// K1: RMSNorm * ada -> fp16
// ---------------------------------------------------------------------------
__global__ __launch_bounds__(256) void rmsnorm_kernel(const float* __restrict__ x,
                                                      const float* __restrict__ scale)
{
    int t = blockIdx.x;
    int n = t >> 14;
    const float* xr = x + (size_t)t * DM;
    float v[3]; float ss = 0.f;
    #pragma unroll
    for (int i = 0; i < 3; i++) { v[i] = xr[threadIdx.x + 256 * i]; ss += v[i] * v[i]; }
    __shared__ float red[8];
    #pragma unroll
    for (int o = 16; o; o >>= 1) ss += __shfl_xor_sync(0xffffffffu, ss, o);
    if ((threadIdx.x & 31) == 0) red[threadIdx.x >> 5] = ss;
    __syncthreads();
    if (threadIdx.x == 0) {
        float r = 0.f;
        #pragma unroll
        for (int i = 0; i < 8; i++) r += red[i];
        red[0] = r;
    }
    __syncthreads();
    float inv = rsqrtf(red[0] * (1.0f / DM) + EPSV);
    const float* sc = scale + (size_t)n * DM;
    #pragma unroll
    for (int i = 0; i < 3; i++) {
        int c = threadIdx.x + 256 * i;
        g_h[(size_t)t * DM + c] = __float2half(v[i] * sc[c] * inv);
    }
}

// ---------------------------------------------------------------------------
// K2: weight split fp32 -> fp16 hi/lo (optional row interleave for ff_up)
// ---------------------------------------------------------------------------
__global__ __launch_bounds__(256) void wsplit_kernel(const float* __restrict__ w,
                                                     __half* __restrict__ hi,
                                                     __half* __restrict__ lo,
                                                     int n, int rowlen, int perm)
{
    int i = blockIdx.x * 256 + threadIdx.x;
    if (i >= n) return;
    int dst = i;
    if (perm) {
        int r = i / rowlen, c = i % rowlen;
        int dr = (r < DFF) ? (2 * r) : (2 * (r - DFF) + 1);
        dst = dr * rowlen + c;
    }
    wsplit2(w[i], &hi[dst], &lo[dst]);
}

// ---------------------------------------------------------------------------
// K3: fused attention (gather q,k + norm + RoPE + softmax + PV + fp16 store)
// ---------------------------------------------------------------------------
#define ATT_PAD  68
#define ATT_SMEM (2 * 64 * ATT_PAD * 4 + 64 * 64 * 4)   // 51200

__global__ __launch_bounds__(64) void attn_kernel(const float* __restrict__ pos,
                                                  const float* __restrict__ attn_scale,
                                                  const float* __restrict__ rope_freqs)
{
    extern __shared__ __align__(16) float sm[];
    float* qR = sm;
    float* kR = sm + 64 * ATT_PAD;
    float* vs = sm + 2 * 64 * ATT_PAD;

    const int b   = blockIdx.x;
    const int rem = b % (NHEADS * 256);
    const int h   = rem >> 8;
    const int w   = rem & 255;
    const bool left = ((w & 15) == 0), top = ((w >> 4) == 0);
    const int tid = threadIdx.x;

    const float* vb = g_vw + (size_t)b * 4096;
    #pragma unroll
    for (int i = tid; i < 1024; i += 64) {
        int r = i >> 4, c4 = (i & 15) << 2;
        int t = win_token(b, r);
        const float* qk = g_qkv + (size_t)t * (2 * DM) + h * DHEAD + c4;
        float4 qv = *(const float4*)qk;
        float4 kv = *(const float4*)(qk + DM);
        float4 vv = *(const float4*)(vb + (i << 2));
        *(float4*)(qR + r * ATT_PAD + c4) = qv;
        *(float4*)(kR + r * ATT_PAD + c4) = kv;
        *(float4*)(vs + r * 64 + c4)      = vv;
    }
    __syncthreads();

    {
        float* qrow = qR + tid * ATT_PAD;
        float* krow = kR + tid * ATT_PAD;
        float sq = 0.f, sk = 0.f;
        #pragma unroll
        for (int e = 0; e < 64; e++) { float a = qrow[e], c = krow[e]; sq += a * a; sk += c * c; }
        float ssh = sqrtf(attn_scale[h]);
        float rq = ssh * rsqrtf(sq + EPSV);
        float rk = ssh * rsqrtf(sk + EPSV);

        int t = win_token(b, tid);
        float p0 = pos[(size_t)t * 2 + 0];
        float p1 = pos[(size_t)t * 2 + 1];
        #pragma unroll
        for (int e = 0; e < 16; e++) {
            float freq = rope_freqs[h * 8 + (e & 7)];
            float th = (e < 8 ? p0 : p1) * freq;
            float c = cosf(th), s = sinf(th);
            float q1 = qrow[e] * rq, q2 = qrow[e + 16] * rq;
            float k1 = krow[e] * rk, k2 = krow[e + 16] * rk;
            qrow[e]      = q1 * c - q2 * s;
            qrow[e + 16] = q2 * c + q1 * s;
            krow[e]      = k1 * c - k2 * s;
            krow[e + 16] = k2 * c + k1 * s;
        }
        #pragma unroll
        for (int e = 32; e < 64; e++) { qrow[e] *= rq; krow[e] *= rk; }
    }
    __syncthreads();

    float sarr[64];
    #pragma unroll
    for (int k = 0; k < 64; k++) sarr[k] = 0.f;
    const float* qrow = qR + tid * ATT_PAD;
    for (int e = 0; e < 64; e += 4) {
        float q0 = qrow[e], q1 = qrow[e + 1], q2 = qrow[e + 2], q3 = qrow[e + 3];
        #pragma unroll
        for (int k = 0; k < 64; k++) {
            float4 kv = *(const float4*)(kR + k * ATT_PAD + e);
            sarr[k] += q0 * kv.x + q1 * kv.y + q2 * kv.z + q3 * kv.w;
        }
    }

    int qh = tid >> 3, qw_ = tid & 7;
    bool qa = qh < SHIFT, ql = qw_ < SHIFT;
    float mx = -3.402823466e38f;
    #pragma unroll
    for (int k = 0; k < 64; k++) {
        int kh = k >> 3, kw = k & 7;
        bool ka = kh < SHIFT, kl = kw < SHIFT;
        bool m = (!left && !top)
               || (left && top && (ql == kl) && (qa == ka))
               || (left && !top && (ql == kl))
               || (!left && top && (qa == ka));
        if (!m) sarr[k] = -3.402823466e38f;
        mx = fmaxf(mx, sarr[k]);
    }
    float sum = 0.f;
    #pragma unroll
    for (int k = 0; k < 64; k++) {
        float p = __expf(sarr[k] - mx);
        sarr[k] = p;
        sum += p;
    }
    float inv = 1.0f / sum;

    float* orow = qR + tid * ATT_PAD;
    for (int e = 0; e < 64; e += 4) {
        float ax = 0.f, ay = 0.f, az = 0.f, aw = 0.f;
        #pragma unroll
        for (int k = 0; k < 64; k++) {
            float4 vv = *(const float4*)(vs + k * 64 + e);
            float p = sarr[k];
            ax += p * vv.x; ay += p * vv.y; az += p * vv.z; aw += p * vv.w;
        }
        orow[e] = ax * inv; orow[e + 1] = ay * inv;
        orow[e + 2] = az * inv; orow[e + 3] = aw * inv;
    }
    __syncthreads();

    #pragma unroll
    for (int i = tid; i < 1024; i += 64) {
        int r = i >> 4, c4 = (i & 15) << 2;
        int t = win_token(b, r);
        size_t dst = (size_t)t * DM + h * DHEAD + c4;
        const float* src = qR + r * ATT_PAD + c4;
        __half h4[4];
        #pragma unroll
        for (int j = 0; j < 4; j++) h4[j] = __float2half(src[j]);
        *(uint2*)&g_oi[dst] = *(uint2*)h4;
    }
}

// ---------------------------------------------------------------------------
// host
// ---------------------------------------------------------------------------
static void launch_hgemm(const __half* A, const __half* Bh, const __half* Bl,
                         const float* D, float* C, int M, int N, int K,
                         int ldc, int mode)
{
    dim3 grid(N / 128, M / 128);
    hgemm_kernel<<<grid, 256, GEMM_SMEM>>>(A, Bh, Bl, D, C, M, N, K, ldc, mode);
}

extern "C" void kernel_launch(void* const* d_in, const int* in_sizes, int n_in,
                              void* d_out, int out_size)
{
    const float* x          = (const float*)d_in[0];
    const float* pos        = (const float*)d_in[1];
    const float* cond       = (const float*)d_in[2];
    const float* ada1_w     = (const float*)d_in[3];
    const float* qkv_w      = (const float*)d_in[4];
    const float* attn_scale = (const float*)d_in[5];
    const float* rope_freqs = (const float*)d_in[6];
    const float* out_w      = (const float*)d_in[7];
    const float* ada2_w     = (const float*)d_in[8];
    const float* ff_up_w    = (const float*)d_in[9];
    const float* ff_down_w  = (const float*)d_in[10];
    float* out = (float*)d_out;

    cudaFuncSetAttribute(hgemm_kernel, cudaFuncAttributeMaxDynamicSharedMemorySize, GEMM_SMEM);
    cudaFuncSetAttribute(attn_kernel, cudaFuncAttributeMaxDynamicSharedMemorySize, ATT_SMEM);

    float *p_scale1, *p_scale2, *p_qkv, *p_x2;
    __half *p_h, *p_oi, *p_a, *p_wh, *p_wl;
    cudaGetSymbolAddress((void**)&p_scale1, g_scale1);
    cudaGetSymbolAddress((void**)&p_scale2, g_scale2);
    cudaGetSymbolAddress((void**)&p_qkv,    g_qkv);
    cudaGetSymbolAddress((void**)&p_x2,     g_x2);
    cudaGetSymbolAddress((void**)&p_h,      g_h);
    cudaGetSymbolAddress((void**)&p_oi,     g_oi);
    cudaGetSymbolAddress((void**)&p_a,      g_a);
    cudaGetSymbolAddress((void**)&p_wh,     g_w_hi);
    cudaGetSymbolAddress((void**)&p_wl,     g_w_lo);

    const int OQKV = 0;
    const int OOUT = OQKV + W_QKV_SZ;
    const int OUP  = OOUT + W_OUT_SZ;
    const int ODN  = OUP + W_UP_SZ;

    wsplit_kernel<<<(W_QKV_SZ + 255) / 256, 256>>>(qkv_w,     p_wh + OQKV, p_wl + OQKV, W_QKV_SZ, DM, 0);
    wsplit_kernel<<<(W_OUT_SZ + 255) / 256, 256>>>(out_w,     p_wh + OOUT, p_wl + OOUT, W_OUT_SZ, DM, 0);
    wsplit_kernel<<<(W_UP_SZ  + 255) / 256, 256>>>(ff_up_w,   p_wh + OUP,  p_wl + OUP,  W_UP_SZ,  DM, 1);
    wsplit_kernel<<<(W_DN_SZ  + 255) / 256, 256>>>(ff_down_w, p_wh + ODN,  p_wl + ODN,  W_DN_SZ,  DFF, 0);

    ada_kernel<<<768, 256>>>(cond, ada1_w, ada2_w);
    rmsnorm_kernel<<<TOKENS, 256>>>(x, p_scale1);
    // qkv: q,k -> g_qkv (ldc=1536); v -> scatter to g_vw
    launch_hgemm(p_h, p_wh + OQKV, p_wl + OQKV, nullptr, p_qkv,
                 TOKENS, 3 * DM, DM, 2 * DM, 2);
    // fused qk-transform + attention + unwindow
    attn_kernel<<<NWIN, 64, ATT_SMEM>>>(pos, attn_scale, rope_freqs);
    launch_hgemm(p_oi, p_wh + OOUT, p_wl + OOUT, x, p_x2,
                 TOKENS, DM, DM, DM, 0);
    rmsnorm_kernel<<<TOKENS, 256>>>(p_x2, p_scale2);
    // ff_up with fused gated GELU (interleaved weights) -> g_a
    launch_hgemm(p_h, p_wh + OUP, p_wl + OUP, nullptr, nullptr,
                 TOKENS, 2 * DFF, DM, 2 * DFF, 1);
    launch_hgemm(p_a, p_wh + ODN, p_wl + ODN, p_x2, out,
                 TOKENS, DM, DFF, DM, 0);
}

// round 8
// speedup vs baseline: 1.9898x; 1.4720x over previous
#include <cuda_runtime.h>
#include <cuda_bf16.h>
#include <cuda_fp16.h>
#include <math.h>
#include <stdint.h>

// ---------------------------------------------------------------------------
// Problem constants
// ---------------------------------------------------------------------------
#define NBATCH   4
#define HDIM     128
#define WDIM     128
#define DM       768
#define NHEADS   12
#define DHEAD    64
#define DFF      2048
#define DC       768
#define WS       8
#define SHIFT    4
#define TOKENS   (NBATCH * HDIM * WDIM)          // 65536
#define NWIN     (NBATCH * NHEADS * 16 * 16)     // 12288
#define EPSV     1e-6f

// ---------------------------------------------------------------------------
// Scratch
// ---------------------------------------------------------------------------
#define W_QKV_SZ (3 * DM * DM)
#define W_OUT_SZ (DM * DM)
#define W_UP_SZ  (2 * DFF * DM)
#define W_DN_SZ  (DM * DFF)
#define W_TOTAL  (W_QKV_SZ + W_OUT_SZ + W_UP_SZ + W_DN_SZ)

__device__ float g_scale1[NBATCH * DM];
__device__ float g_scale2[NBATCH * DM];
__device__ float g_qkv [(size_t)TOKENS * 2 * DM];     // q,k fp32 (ldc=1536)
__device__ float g_vw  [(size_t)NWIN * 64 * 64];      // v windowed fp32
__device__ float g_x2  [(size_t)TOKENS * DM];

__device__ __half g_h  [(size_t)TOKENS * DM];         // activations fp16
__device__ __half g_oi [(size_t)TOKENS * DM];
__device__ __half g_a  [(size_t)TOKENS * DFF];
__device__ __half g_w  [W_TOTAL];                     // weights fp16 (single)

// ---------------------------------------------------------------------------
// PTX helpers (sm_80+ features only; legal under compute_103)
// ---------------------------------------------------------------------------
__device__ __forceinline__ uint32_t smem_to_u32(const void* p) {
    uint32_t a;
    asm("{ .reg .u64 t; cvta.to.shared.u64 t, %1; cvt.u32.u64 %0, t; }" : "=r"(a) : "l"(p));
    return a;
}
#define CP_ASYNC16(sa, gp) \
    asm volatile("cp.async.cg.shared.global [%0], [%1], 16;" :: "r"(sa), "l"(gp))
#define CP_COMMIT() asm volatile("cp.async.commit_group;" ::: "memory")
#define CP_WAIT1()  asm volatile("cp.async.wait_group 1;" ::: "memory")
#define CP_WAIT0()  asm volatile("cp.async.wait_group 0;" ::: "memory")

__device__ __forceinline__ void ldsm_x4(uint32_t& r0, uint32_t& r1, uint32_t& r2,
                                        uint32_t& r3, uint32_t addr) {
    asm volatile("ldmatrix.sync.aligned.m8n8.x4.shared.b16 {%0,%1,%2,%3}, [%4];"
                 : "=r"(r0), "=r"(r1), "=r"(r2), "=r"(r3) : "r"(addr));
}
__device__ __forceinline__ void mma_f16(float c[4], const uint32_t a[4],
                                        const uint32_t b[2]) {
    asm volatile("mma.sync.aligned.m16n8k16.row.col.f32.f16.f16.f32 "
                 "{%0,%1,%2,%3},{%4,%5,%6,%7},{%8,%9},{%0,%1,%2,%3};"
                 : "+f"(c[0]), "+f"(c[1]), "+f"(c[2]), "+f"(c[3])
                 : "r"(a[0]), "r"(a[1]), "r"(a[2]), "r"(a[3]),
                   "r"(b[0]), "r"(b[1]));
}

// window-scatter address helper (roll +4,+4 then 8x8 windows)
__device__ __forceinline__ size_t win_addr(int t, int h, int e) {
    int n = t >> 14;
    int y = (t >> 7) & 127;
    int x = t & 127;
    int Y = (y + SHIFT) & 127, X = (x + SHIFT) & 127;
    int wyx  = ((Y >> 3) << 4) + (X >> 3);
    int spos = ((Y & 7) << 3) + (X & 7);
    return ((size_t)((n * NHEADS + h) * 256 + wyx)) * 4096 + (size_t)spos * 64 + e;
}

// inverse: window b, slot r -> token index
__device__ __forceinline__ int win_token(int b, int r) {
    int n   = b / (NHEADS * 256);
    int rem = b % (NHEADS * 256);
    int w   = rem & 255;
    int Y = ((w >> 4) << 3) + (r >> 3);
    int X = ((w & 15) << 3) + (r & 7);
    int y = (Y - SHIFT) & 127, x = (X - SHIFT) & 127;
    return (n << 14) + (y << 7) + x;
}

// ---------------------------------------------------------------------------
// GEMM: C = (D?D:0) + A @ B^T.  A,B single fp16, fp32 accum.
// CTA tile 128x256x32, 8 warps (2m x 4n), warp tile 64x64.
// mode 0: plain (+residual)   mode 1: fused gated-GELU -> g_a
// mode 2: qkv (cols<1536 -> C fp32; cols>=1536 -> scatter V to g_vw)
// ---------------------------------------------------------------------------
#define BKC      32
#define PADK     40
#define TILE_A_E (128 * PADK)
#define TILE_B_E (256 * PADK)
#define STAGE_E  (TILE_A_E + TILE_B_E)       // 15360 elems
#define GEMM_SMEM (2 * STAGE_E * 2)          // 61440 bytes

__global__ __launch_bounds__(256) void hgemm_kernel(
    const __half* __restrict__ A, const __half* __restrict__ B,
    const float* __restrict__ Dres, float* __restrict__ C,
    int M, int N, int K, int ldc, int mode)
{
    extern __shared__ __align__(128) char smem[];
    const uint32_t sbase = smem_to_u32(smem);
    const int tid = threadIdx.x, lane = tid & 31, wid = tid >> 5;
    const int wm = wid >> 2, wn = wid & 3;
    const size_t bm = (size_t)blockIdx.y * 128;
    const size_t bn = (size_t)blockIdx.x * 256;

    const __half* Ab = A + bm * (size_t)K;
    const __half* Bb = B + bn * (size_t)K;

    float acc[4][8][4];
    #pragma unroll
    for (int i = 0; i < 4; i++)
        #pragma unroll
        for (int j = 0; j < 8; j++)
            #pragma unroll
            for (int l = 0; l < 4; l++) acc[i][j][l] = 0.f;

    const int nstage = K / BKC;

    // A: 512 chunks (2 iters), B: 1024 chunks (4 iters); chunk = 16B
    auto issue = [&](int st) {
        const int k0 = st * BKC;
        const uint32_t sb = sbase + (uint32_t)((st & 1) * STAGE_E * 2);
        #pragma unroll
        for (int i = 0; i < 2; i++) {
            int idx = tid + i * 256;
            int row = idx >> 2, seg = (idx & 3) << 3;
            const __half* gp = Ab + (size_t)row * K + k0 + seg;
            uint32_t sa = sb + (uint32_t)((row * PADK + seg) * 2);
            CP_ASYNC16(sa, gp);
        }
        #pragma unroll
        for (int i = 0; i < 4; i++) {
            int idx = tid + i * 256;
            int row = idx >> 2, seg = (idx & 3) << 3;
            const __half* gp = Bb + (size_t)row * K + k0 + seg;
            uint32_t sa = sb + (uint32_t)((TILE_A_E + row * PADK + seg) * 2);
            CP_ASYNC16(sa, gp);
        }
        CP_COMMIT();
    };

    issue(0);
    if (nstage > 1) issue(1);

    const int a_r = lane & 15, a_h = (lane >> 4) << 3;
    const int b_r = (lane & 7) + ((lane & 16) >> 1);
    const int b_k = lane & 8;

    for (int st = 0; st < nstage; st++) {
        if (st + 1 < nstage) { CP_WAIT1(); } else { CP_WAIT0(); }
        __syncthreads();

        const uint32_t sb = sbase + (uint32_t)((st & 1) * STAGE_E * 2);
        const uint32_t sA = sb;
        const uint32_t sB = sb + TILE_A_E * 2;

        #pragma unroll
        for (int kk = 0; kk < BKC; kk += 16) {
            uint32_t a[4][4], bh[8][2];
            #pragma unroll
            for (int mt = 0; mt < 4; mt++)
                ldsm_x4(a[mt][0], a[mt][1], a[mt][2], a[mt][3],
                        sA + (uint32_t)(((wm * 64 + mt * 16 + a_r) * PADK + kk + a_h) * 2));
            #pragma unroll
            for (int p = 0; p < 4; p++) {
                uint32_t r0, r1, r2, r3;
                ldsm_x4(r0, r1, r2, r3,
                        sB + (uint32_t)(((wn * 64 + p * 16 + b_r) * PADK + kk + b_k) * 2));
                bh[p * 2][0] = r0; bh[p * 2][1] = r1;
                bh[p * 2 + 1][0] = r2; bh[p * 2 + 1][1] = r3;
            }
            #pragma unroll
            for (int mt = 0; mt < 4; mt++)
                #pragma unroll
                for (int nt = 0; nt < 8; nt++)
                    mma_f16(acc[mt][nt], a[mt], bh[nt]);
        }
        __syncthreads();
        if (st + 2 < nstage) issue(st + 2);
    }

    const int er = lane >> 2, ec = (lane & 3) * 2;

    if (mode == 1) {
        // fused gated GELU: col pair (even,odd) = (a_j, g_j); j = col/2
        #pragma unroll
        for (int mt = 0; mt < 4; mt++) {
            size_t r0 = bm + wm * 64 + mt * 16 + er;
            size_t r1 = r0 + 8;
            #pragma unroll
            for (int nt = 0; nt < 8; nt++) {
                int col = (int)bn + wn * 64 + nt * 8 + ec;
                int j = col >> 1;
                float a0 = acc[mt][nt][0], gg0 = acc[mt][nt][1];
                float a1 = acc[mt][nt][2], gg1 = acc[mt][nt][3];
                float v0 = a0 * (gg0 * 0.5f * (1.0f + erff(gg0 * 0.70710678118654752f)));
                float v1 = a1 * (gg1 * 0.5f * (1.0f + erff(gg1 * 0.70710678118654752f)));
                g_a[r0 * DFF + j] = __float2half(v0);
                g_a[r1 * DFF + j] = __float2half(v1);
            }
        }
        return;
    }

    if (mode == 2 && bn >= 1536) {
        // V region: scatter straight into windowed layout
        #pragma unroll
        for (int mt = 0; mt < 4; mt++) {
            int t0 = (int)bm + wm * 64 + mt * 16 + er;
            int t1 = t0 + 8;
            #pragma unroll
            for (int nt = 0; nt < 8; nt++) {
                int col = (int)bn + wn * 64 + nt * 8 + ec;
                int h = (col - 1536) >> 6;
                int e = col & 63;
                float2 v0 = make_float2(acc[mt][nt][0], acc[mt][nt][1]);
                float2 v1 = make_float2(acc[mt][nt][2], acc[mt][nt][3]);
                *(float2*)&g_vw[win_addr(t0, h, e)] = v0;
                *(float2*)&g_vw[win_addr(t1, h, e)] = v1;
            }
        }
        return;
    }

    #pragma unroll
    for (int mt = 0; mt < 4; mt++) {
        size_t row0 = bm + wm * 64 + mt * 16 + er;
        #pragma unroll
        for (int nt = 0; nt < 8; nt++) {
            size_t col = bn + wn * 64 + nt * 8 + ec;
            float* p0 = C + row0 * (size_t)ldc + col;
            float* p1 = C + (row0 + 8) * (size_t)ldc + col;
            float2 v0 = make_float2(acc[mt][nt][0], acc[mt][nt][1]);
            float2 v1 = make_float2(acc[mt][nt][2], acc[mt][nt][3]);
            if (Dres) {
                const float2 d0 = *(const float2*)(Dres + row0 * (size_t)ldc + col);
                const float2 d1 = *(const float2*)(Dres + (row0 + 8) * (size_t)ldc + col);
                v0.x += d0.x; v0.y += d0.y; v1.x += d1.x; v1.y += d1.y;
            }
            *(float2*)p0 = v0;
            *(float2*)p1 = v1;
        }
    }
}

// ---------------------------------------------------------------------------
// K0: ada scales
// ---------------------------------------------------------------------------
__global__ void ada_kernel(const float* __restrict__ cond,
                           const float* __restrict__ w1,
                           const float* __restrict__ w2)
{
    int gw   = (blockIdx.x * blockDim.x + threadIdx.x) >> 5;
    int lane = threadIdx.x & 31;
    if (gw >= 2 * NBATCH * DM) return;
    int which = gw / (NBATCH * DM);
    int rem   = gw % (NBATCH * DM);
    int n = rem / DM, d = rem % DM;
    const float* w  = which ? w2 : w1;
    const float* cr = cond + n * DC;
    const float* wr = w + (size_t)d * DC;
    float s = 0.f;
    for (int i = lane; i < DC; i += 32) s += cr[i] * wr[i];
    #pragma unroll
    for (int o = 16; o; o >>= 1) s += __shfl_xor_sync(0xffffffffu, s, o);
    if (lane == 0) (which ? g_scale2 : g_scale1)[rem] = s + 1.0f;
}

// ---------------------------------------------------------------------------
// K1: RMSNorm * ada -> fp16
// ---------------------------------------------------------------------------
__global__ __launch_bounds__(256) void rmsnorm_kernel(const float* __restrict__ x,
                                                      const float* __restrict__ scale)
{
    int t = blockIdx.x;
    int n = t >> 14;
    const float* xr = x + (size_t)t * DM;
    float v[3]; float ss = 0.f;
    #pragma unroll
    for (int i = 0; i < 3; i++) { v[i] = xr[threadIdx.x + 256 * i]; ss += v[i] * v[i]; }
    __shared__ float red[8];
    #pragma unroll
    for (int o = 16; o; o >>= 1) ss += __shfl_xor_sync(0xffffffffu, ss, o);
    if ((threadIdx.x & 31) == 0) red[threadIdx.x >> 5] = ss;
    __syncthreads();
    if (threadIdx.x == 0) {
        float r = 0.f;
        #pragma unroll
        for (int i = 0; i < 8; i++) r += red[i];
        red[0] = r;
    }
    __syncthreads();
    float inv = rsqrtf(red[0] * (1.0f / DM) + EPSV);
    const float* sc = scale + (size_t)n * DM;
    #pragma unroll
    for (int i = 0; i < 3; i++) {
        int c = threadIdx.x + 256 * i;
        g_h[(size_t)t * DM + c] = __float2half(v[i] * sc[c] * inv);
    }
}

// ---------------------------------------------------------------------------
// K2: weight convert fp32 -> fp16 (optional row interleave for ff_up)
// ---------------------------------------------------------------------------
__global__ __launch_bounds__(256) void wconv_kernel(const float* __restrict__ w,
                                                    __half* __restrict__ dsth,
                                                    int n, int rowlen, int perm)
{
    int i = blockIdx.x * 256 + threadIdx.x;
    if (i >= n) return;
    int dst = i;
    if (perm) {
        int r = i / rowlen, c = i % rowlen;
        int dr = (r < DFF) ? (2 * r) : (2 * (r - DFF) + 1);
        dst = dr * rowlen + c;
    }
    dsth[dst] = __float2half(w[i]);
}

// ---------------------------------------------------------------------------
// K3: fused attention (gather q,k + norm + RoPE + softmax + PV + fp16 store)
// ---------------------------------------------------------------------------
#define ATT_PAD  68
#define ATT_SMEM (2 * 64 * ATT_PAD * 4 + 64 * 64 * 4)   // 51200

__global__ __launch_bounds__(64) void attn_kernel(const float* __restrict__ pos,
                                                  const float* __restrict__ attn_scale,
                                                  const float* __restrict__ rope_freqs)
{
    extern __shared__ __align__(16) float sm[];
    float* qR = sm;
    float* kR = sm + 64 * ATT_PAD;
    float* vs = sm + 2 * 64 * ATT_PAD;

    const int b   = blockIdx.x;
    const int rem = b % (NHEADS * 256);
    const int h   = rem >> 8;
    const int w   = rem & 255;
    const bool left = ((w & 15) == 0), top = ((w >> 4) == 0);
    const int tid = threadIdx.x;

    const float* vb = g_vw + (size_t)b * 4096;
    #pragma unroll
    for (int i = tid; i < 1024; i += 64) {
        int r = i >> 4, c4 = (i & 15) << 2;
        int t = win_token(b, r);
        const float* qk = g_qkv + (size_t)t * (2 * DM) + h * DHEAD + c4;
        float4 qv = *(const float4*)qk;
        float4 kv = *(const float4*)(qk + DM);
        float4 vv = *(const float4*)(vb + (i << 2));
        *(float4*)(qR + r * ATT_PAD + c4) = qv;
        *(float4*)(kR + r * ATT_PAD + c4) = kv;
        *(float4*)(vs + r * 64 + c4)      = vv;
    }
    __syncthreads();

    {
        float* qrow = qR + tid * ATT_PAD;
        float* krow = kR + tid * ATT_PAD;
        float sq = 0.f, sk = 0.f;
        #pragma unroll
        for (int e = 0; e < 64; e++) { float a = qrow[e], c = krow[e]; sq += a * a; sk += c * c; }
        float ssh = sqrtf(attn_scale[h]);
        float rq = ssh * rsqrtf(sq + EPSV);
        float rk = ssh * rsqrtf(sk + EPSV);

        int t = win_token(b, tid);
        float p0 = pos[(size_t)t * 2 + 0];
        float p1 = pos[(size_t)t * 2 + 1];
        #pragma unroll
        for (int e = 0; e < 16; e++) {
            float freq = rope_freqs[h * 8 + (e & 7)];
            float th = (e < 8 ? p0 : p1) * freq;
            float c = cosf(th), s = sinf(th);
            float q1 = qrow[e] * rq, q2 = qrow[e + 16] * rq;
            float k1 = krow[e] * rk, k2 = krow[e + 16] * rk;
            qrow[e]      = q1 * c - q2 * s;
            qrow[e + 16] = q2 * c + q1 * s;
            krow[e]      = k1 * c - k2 * s;
            krow[e + 16] = k2 * c + k1 * s;
        }
        #pragma unroll
        for (int e = 32; e < 64; e++) { qrow[e] *= rq; krow[e] *= rk; }
    }
    __syncthreads();

    float sarr[64];
    #pragma unroll
    for (int k = 0; k < 64; k++) sarr[k] = 0.f;
    const float* qrow = qR + tid * ATT_PAD;
    for (int e = 0; e < 64; e += 4) {
        float q0 = qrow[e], q1 = qrow[e + 1], q2 = qrow[e + 2], q3 = qrow[e + 3];
        #pragma unroll
        for (int k = 0; k < 64; k++) {
            float4 kv = *(const float4*)(kR + k * ATT_PAD + e);
            sarr[k] += q0 * kv.x + q1 * kv.y + q2 * kv.z + q3 * kv.w;
        }
    }

    int qh = tid >> 3, qw_ = tid & 7;
    bool qa = qh < SHIFT, ql = qw_ < SHIFT;
    float mx = -3.402823466e38f;
    #pragma unroll
    for (int k = 0; k < 64; k++) {
        int kh = k >> 3, kw = k & 7;
        bool ka = kh < SHIFT, kl = kw < SHIFT;
        bool m = (!left && !top)
               || (left && top && (ql == kl) && (qa == ka))
               || (left && !top && (ql == kl))
               || (!left && top && (qa == ka));
        if (!m) sarr[k] = -3.402823466e38f;
        mx = fmaxf(mx, sarr[k]);
    }
    float sum = 0.f;
    #pragma unroll
    for (int k = 0; k < 64; k++) {
        float p = __expf(sarr[k] - mx);
        sarr[k] = p;
        sum += p;
    }
    float inv = 1.0f / sum;

    float* orow = qR + tid * ATT_PAD;
    for (int e = 0; e < 64; e += 4) {
        float ax = 0.f, ay = 0.f, az = 0.f, aw = 0.f;
        #pragma unroll
        for (int k = 0; k < 64; k++) {
            float4 vv = *(const float4*)(vs + k * 64 + e);
            float p = sarr[k];
            ax += p * vv.x; ay += p * vv.y; az += p * vv.z; aw += p * vv.w;
        }
        orow[e] = ax * inv; orow[e + 1] = ay * inv;
        orow[e + 2] = az * inv; orow[e + 3] = aw * inv;
    }
    __syncthreads();

    #pragma unroll
    for (int i = tid; i < 1024; i += 64) {
        int r = i >> 4, c4 = (i & 15) << 2;
        int t = win_token(b, r);
        size_t dst = (size_t)t * DM + h * DHEAD + c4;
        const float* src = qR + r * ATT_PAD + c4;
        __half h4[4];
        #pragma unroll
        for (int j = 0; j < 4; j++) h4[j] = __float2half(src[j]);
        *(uint2*)&g_oi[dst] = *(uint2*)h4;
    }
}

// ---------------------------------------------------------------------------
// host
// ---------------------------------------------------------------------------
static void launch_hgemm(const __half* A, const __half* B,
                         const float* D, float* C, int M, int N, int K,
                         int ldc, int mode)
{
    dim3 grid(N / 256, M / 128);
    hgemm_kernel<<<grid, 256, GEMM_SMEM>>>(A, B, D, C, M, N, K, ldc, mode);
}

extern "C" void kernel_launch(void* const* d_in, const int* in_sizes, int n_in,
                              void* d_out, int out_size)
{
    const float* x          = (const float*)d_in[0];
    const float* pos        = (const float*)d_in[1];
    const float* cond       = (const float*)d_in[2];
    const float* ada1_w     = (const float*)d_in[3];
    const float* qkv_w      = (const float*)d_in[4];
    const float* attn_scale = (const float*)d_in[5];
    const float* rope_freqs = (const float*)d_in[6];
    const float* out_w      = (const float*)d_in[7];
    const float* ada2_w     = (const float*)d_in[8];
    const float* ff_up_w    = (const float*)d_in[9];
    const float* ff_down_w  = (const float*)d_in[10];
    float* out = (float*)d_out;

    cudaFuncSetAttribute(hgemm_kernel, cudaFuncAttributeMaxDynamicSharedMemorySize, GEMM_SMEM);
    cudaFuncSetAttribute(attn_kernel, cudaFuncAttributeMaxDynamicSharedMemorySize, ATT_SMEM);

    float *p_scale1, *p_scale2, *p_qkv, *p_x2;
    __half *p_h, *p_oi, *p_a, *p_w;
    cudaGetSymbolAddress((void**)&p_scale1, g_scale1);
    cudaGetSymbolAddress((void**)&p_scale2, g_scale2);
    cudaGetSymbolAddress((void**)&p_qkv,    g_qkv);
    cudaGetSymbolAddress((void**)&p_x2,     g_x2);
    cudaGetSymbolAddress((void**)&p_h,      g_h);
    cudaGetSymbolAddress((void**)&p_oi,     g_oi);
    cudaGetSymbolAddress((void**)&p_a,      g_a);
    cudaGetSymbolAddress((void**)&p_w,      g_w);

    const int OQKV = 0;
    const int OOUT = OQKV + W_QKV_SZ;
    const int OUP  = OOUT + W_OUT_SZ;
    const int ODN  = OUP + W_UP_SZ;

    wconv_kernel<<<(W_QKV_SZ + 255) / 256, 256>>>(qkv_w,     p_w + OQKV, W_QKV_SZ, DM, 0);
    wconv_kernel<<<(W_OUT_SZ + 255) / 256, 256>>>(out_w,     p_w + OOUT, W_OUT_SZ, DM, 0);
    wconv_kernel<<<(W_UP_SZ  + 255) / 256, 256>>>(ff_up_w,   p_w + OUP,  W_UP_SZ,  DM, 1);
    wconv_kernel<<<(W_DN_SZ  + 255) / 256, 256>>>(ff_down_w, p_w + ODN,  W_DN_SZ,  DFF, 0);

    ada_kernel<<<768, 256>>>(cond, ada1_w, ada2_w);
    rmsnorm_kernel<<<TOKENS, 256>>>(x, p_scale1);
    // qkv: q,k -> g_qkv (ldc=1536); v -> scatter to g_vw
    launch_hgemm(p_h, p_w + OQKV, nullptr, p_qkv, TOKENS, 3 * DM, DM, 2 * DM, 2);
    // fused qk-transform + attention + unwindow
    attn_kernel<<<NWIN, 64, ATT_SMEM>>>(pos, attn_scale, rope_freqs);
    launch_hgemm(p_oi, p_w + OOUT, x, p_x2, TOKENS, DM, DM, DM, 0);
    rmsnorm_kernel<<<TOKENS, 256>>>(p_x2, p_scale2);
    // ff_up with fused gated GELU (interleaved weights) -> g_a
    launch_hgemm(p_h, p_w + OUP, nullptr, nullptr, TOKENS, 2 * DFF, DM, 2 * DFF, 1);
    launch_hgemm(p_a, p_w + ODN, p_x2, out, TOKENS, DM, DFF, DM, 0);
}